// round 7
// baseline (speedup 1.0000x reference)
#include <cuda_runtime.h>
#include <cuda_bf16.h>
#include <math.h>
#include <stdint.h>

// ---------------------------------------------------------------------------
// PredictiveColumn on GB300 via mma.sync bf16.
//   build_sc       : g_Sc band + zero norm
//   transpose_prep : bf16 W / W^T / V^T via tiled smem transpose
//   convert_bu     : bottom_up fp32 -> bf16
//   rowprep        : exact kWTA via radix-256 histogram, phi(bf16), phi'(bf16),
//                    base (lateral stencil + td - 4x - L1)
//   gemm<1>        : rd  = bu @ V + b_in + base             (B = V^T)
//   gemm<0>        : err = bu - (phi @ W + b_out) -> bf16   (B = W^T)
//   gemm<2>        : sg  = (err @ W^T)*phi' + rd ; ||sg||^2 (B = W)
//   finalize       : out = clip(x + scale*sg, -5, 5)
// ---------------------------------------------------------------------------

#define BDIM 16384
#define DDIM 512
#define KWTA 128
#define NTOT (BDIM*DDIM)

__device__ __nv_bfloat16 g_bu_bf  [NTOT];
__device__ __nv_bfloat16 g_phi_bf [NTOT];
__device__ __nv_bfloat16 g_err_bf [NTOT];
__device__ __nv_bfloat16 g_phid_bf[NTOT];
__device__ float  g_base[NTOT];
__device__ float  g_rd  [NTOT];
__device__ float  g_sg  [NTOT];
__device__ __nv_bfloat16 g_W_bf [DDIM*DDIM];
__device__ __nv_bfloat16 g_Wt_bf[DDIM*DDIM];
__device__ __nv_bfloat16 g_Vt_bf[DDIM*DDIM];
__device__ float  g_Sc[DDIM*8];
__device__ double g_norm2;

// ------------------------------ helpers -----------------------------------
__device__ __forceinline__ uint32_t smem_to_u32(const void* p) {
    uint32_t a;
    asm("{ .reg .u64 t; cvta.to.shared.u64 t, %1; cvt.u32.u64 %0, t; }" : "=r"(a) : "l"(p));
    return a;
}
__device__ __forceinline__ void cpa16(uint32_t dst, const void* src) {
    asm volatile("cp.async.cg.shared.global [%0], [%1], 16;" :: "r"(dst), "l"(src));
}
#define CP_COMMIT() asm volatile("cp.async.commit_group;" ::: "memory")
#define CP_WAIT1()  asm volatile("cp.async.wait_group 1;" ::: "memory")

#define LDMX4(r0, r1, r2, r3, addr) \
    asm volatile("ldmatrix.sync.aligned.m8n8.x4.shared.b16 {%0,%1,%2,%3}, [%4];" \
                 : "=r"(r0), "=r"(r1), "=r"(r2), "=r"(r3) : "r"(addr))

#define MMA_BF16(c, a0, a1, a2, a3, b0, b1) \
    asm volatile("mma.sync.aligned.m16n8k16.row.col.f32.bf16.bf16.f32 " \
                 "{%0,%1,%2,%3}, {%4,%5,%6,%7}, {%8,%9}, {%0,%1,%2,%3};" \
                 : "+f"((c)[0]), "+f"((c)[1]), "+f"((c)[2]), "+f"((c)[3]) \
                 : "r"(a0), "r"(a1), "r"(a2), "r"(a3), "r"(b0), "r"(b1))

// ------------------------------ prep kernels ------------------------------
__global__ __launch_bounds__(256) void build_sc(const float* __restrict__ L,
                                                const float* __restrict__ Lm)
{
    int n = blockIdx.x * 256 + threadIdx.x;
    if (n == 0) g_norm2 = 0.0;
    if (n >= DDIM) return;
#pragma unroll
    for (int d = 0; d < 7; d++) {
        int j = n - 3 + d;
        float v = 0.0f;
        if (j >= 0 && j < DDIM) v = L[(size_t)j*DDIM + n] * Lm[(size_t)j*DDIM + n];
        g_Sc[n*8 + d] = v;
    }
    g_Sc[n*8 + 7] = 0.0f;
}

// tiled transpose: W -> W_bf, Wt_bf ; V -> Vt_bf. 32x32 tiles, block (32,8).
__global__ __launch_bounds__(256) void transpose_prep(const float* __restrict__ W,
                                                      const float* __restrict__ V)
{
    __shared__ float tw[32][33];
    __shared__ float tv[32][33];
    const int tx = threadIdx.x, ty = threadIdx.y;
    const int x0 = blockIdx.x * 32, y0 = blockIdx.y * 32;
#pragma unroll
    for (int r = 0; r < 4; r++) {
        int row = y0 + ty + r*8;
        float w = W[(size_t)row*DDIM + x0 + tx];
        float v = V[(size_t)row*DDIM + x0 + tx];
        tw[ty + r*8][tx] = w;
        tv[ty + r*8][tx] = v;
        g_W_bf[(size_t)row*DDIM + x0 + tx] = __float2bfloat16(w);
    }
    __syncthreads();
#pragma unroll
    for (int r = 0; r < 4; r++) {
        int row = x0 + ty + r*8;
        g_Wt_bf[(size_t)row*DDIM + y0 + tx] = __float2bfloat16(tw[tx][ty + r*8]);
        g_Vt_bf[(size_t)row*DDIM + y0 + tx] = __float2bfloat16(tv[tx][ty + r*8]);
    }
}

__global__ __launch_bounds__(256) void convert_bu(const float4* __restrict__ src)
{
    int i = blockIdx.x * 256 + threadIdx.x;          // 8 floats per thread
    float4 a = src[i*2], b = src[i*2+1];
    __nv_bfloat162 p0 = __float22bfloat162_rn(make_float2(a.x, a.y));
    __nv_bfloat162 p1 = __float22bfloat162_rn(make_float2(a.z, a.w));
    __nv_bfloat162 p2 = __float22bfloat162_rn(make_float2(b.x, b.y));
    __nv_bfloat162 p3 = __float22bfloat162_rn(make_float2(b.z, b.w));
    uint4 o;
    o.x = *(uint32_t*)&p0; o.y = *(uint32_t*)&p1; o.z = *(uint32_t*)&p2; o.w = *(uint32_t*)&p3;
    *(uint4*)(&g_bu_bf[(size_t)i*8]) = o;
}

// ------------------------------ rowprep -----------------------------------
// 512 threads, 1 element each. Exact k-th-largest via 4 radix-256 histogram
// passes; tie resolution by lowest index (matches jax.lax.top_k).
__global__ __launch_bounds__(512) void rowprep(const float* __restrict__ x,
                                               const float* __restrict__ td)
{
    __shared__ int   hist[256];
    __shared__ float phi_s[DDIM];
    __shared__ int   s_b, s_rem;
    __shared__ int   wg[16], we[16];

    const int tid = threadIdx.x;
    const int wid = tid >> 5, lane = tid & 31;
    const size_t rb = (size_t)blockIdx.x * DDIM;
    const unsigned FULL = 0xffffffffu;

    const float v = x[rb + tid];
    uint32_t u = __float_as_uint(v);
    u = (u & 0x80000000u) ? ~u : (u | 0x80000000u);   // order-preserving map

    uint32_t prefix = 0; int rem = KWTA;
#pragma unroll 1
    for (int pass = 0; pass < 4; pass++) {
        const int sh = 24 - 8*pass;
        const bool active = (pass == 0) || ((u >> (sh + 8)) == prefix);
        const int  byte   = (u >> sh) & 255;
        if (tid < 256) hist[tid] = 0;
        __syncthreads();
        if (active) atomicAdd(&hist[byte], 1);
        __syncthreads();
        if (tid < 32) {
            int cum = 0;
            bool done = false;
#pragma unroll 1
            for (int c = 0; c < 8; c++) {
                int bin = 255 - (c*32 + lane);     // lane 0 = highest bin in chunk
                int cnt = hist[bin];
                int p = cnt;
#pragma unroll
                for (int o = 1; o < 32; o <<= 1) {
                    int t2 = __shfl_up_sync(FULL, p, o);
                    if (lane >= o) p += t2;
                }
                int tot = __shfl_sync(FULL, p, 31);
                if (!done) {
                    unsigned hit = __ballot_sync(FULL, cum + p >= rem);
                    if (hit) {
                        int fl = __ffs(hit) - 1;
                        if (lane == fl) { s_b = bin; s_rem = rem - (cum + p - cnt); }
                        done = true;
                    }
                }
                cum += tot;
            }
        }
        __syncthreads();
        prefix = (prefix << 8) | (uint32_t)s_b;
        rem = s_rem;
    }
    // prefix == bit pattern of the KWTA-th largest value
    const bool gt = (u > prefix), eq = (u == prefix);
    unsigned bal_gt = __ballot_sync(FULL, gt);
    unsigned bal_eq = __ballot_sync(FULL, eq);
    if (lane == 0) { wg[wid] = __popc(bal_gt); we[wid] = __popc(bal_eq); }
    __syncthreads();
    int cgt = 0, rank = __popc(bal_eq & ((1u << lane) - 1u));
#pragma unroll
    for (int w = 0; w < 16; w++) { cgt += wg[w]; if (w < wid) rank += we[w]; }
    const int  need = KWTA - cgt;
    const bool m = gt || (eq && rank < need);

    const float inv_sqrt2   = 0.7071067811865476f;
    const float inv_sqrt2pi = 0.3989422804014327f;
    float cdf = 0.5f * (1.0f + erff(v * inv_sqrt2));
    float pdf = expf(-0.5f * v * v) * inv_sqrt2pi;
    float ph = m ? v * cdf : 0.0f;
    float pd = m ? (cdf + v * pdf) : 0.0f;
    phi_s[tid] = ph;
    g_phi_bf [rb + tid] = __float2bfloat16(ph);
    g_phid_bf[rb + tid] = __float2bfloat16(pd);
    __syncthreads();

    float lat = 0.0f;
#pragma unroll
    for (int d = 0; d < 7; d++) {
        int j = tid - 3 + d;
        if (j >= 0 && j < DDIM) lat += phi_s[j] * g_Sc[tid*8 + d];
    }
    float sgn = (v > 0.0f) ? 1.0f : ((v < 0.0f) ? -1.0f : 0.0f);
    g_base[rb + tid] = 0.3f*lat + 3.0f*td[rb + tid] - 4.0f*v - 1e-6f*sgn;
}

// ------------------------------ HMMA GEMM ---------------------------------
// BM=128, BN=128, BK=32; 256 threads = 8 warps (4m x 2n), warp tile 32x64.
// SMEM rows padded to 80B. 3-stage cp.async pipeline, 1 barrier/iter.
#define BM 128
#define BN 128
#define BK 32
#define NKIT (DDIM / BK)     // 16
#define ASTRIDE 80
#define B_OFF   (BM * ASTRIDE)             // 10240
#define BUFBYTES ((BM + BN) * ASTRIDE)     // 20480
#define GSTAGES 3
#define GSMEM (GSTAGES * BUFBYTES)         // 61440

template<int MODE>
__global__ __launch_bounds__(256)
void gemm_hmma(const float* __restrict__ bias, const float* __restrict__ extra)
{
    extern __shared__ char smem[];
    const uint32_t sbase = smem_to_u32(smem);

    const int tid  = threadIdx.x;
    const int wid  = tid >> 5, lane = tid & 31;
    const int wm   = wid & 3;          // m offset 32*wm
    const int wn   = wid >> 2;         // n offset 64*wn
    const int m0   = blockIdx.y * BM;
    const int n0   = blockIdx.x * BN;

    const __nv_bfloat16* A  = (MODE == 1) ? g_bu_bf : (MODE == 0 ? g_phi_bf : g_err_bf);
    const __nv_bfloat16* Bt = (MODE == 1) ? g_Vt_bf : (MODE == 0 ? g_Wt_bf : g_W_bf);

    float acc[2][8][4];
#pragma unroll
    for (int i = 0; i < 2; i++)
#pragma unroll
        for (int j = 0; j < 8; j++)
#pragma unroll
            for (int q = 0; q < 4; q++) acc[i][j][q] = 0.0f;

    auto load_stage = [&](int k0, int buf) {
#pragma unroll
        for (int i = 0; i < 2; i++) {
            int ch = tid * 2 + i;            // 0..511
            int r = ch >> 2, c = ch & 3;
            cpa16(sbase + buf*BUFBYTES + r*ASTRIDE + c*16,
                  (const char*)A + ((size_t)(m0 + r) * DDIM + k0*BK + c*8) * 2);
            cpa16(sbase + buf*BUFBYTES + B_OFF + r*ASTRIDE + c*16,
                  (const char*)Bt + ((size_t)(n0 + r) * DDIM + k0*BK + c*8) * 2);
        }
    };

    load_stage(0, 0); CP_COMMIT();
    load_stage(1, 1); CP_COMMIT();

#pragma unroll 1
    for (int k0 = 0; k0 < NKIT; k0++) {
        const int buf = k0 % GSTAGES;
        CP_WAIT1();                 // stage k0 complete (k0+1 may be in flight)
        __syncthreads();

        const uint32_t abase = sbase + buf*BUFBYTES;
        const uint32_t bbase = abase + B_OFF;
        const int lrow = lane & 15;
#pragma unroll
        for (int ks = 0; ks < 2; ks++) {
            const int lchunk = ks*2 + (lane >> 4);
            uint32_t a[2][4], bf[4][4];
#pragma unroll
            for (int ma = 0; ma < 2; ma++) {
                uint32_t ad = abase + (wm*32 + ma*16 + lrow)*ASTRIDE + lchunk*16;
                LDMX4(a[ma][0], a[ma][1], a[ma][2], a[ma][3], ad);
            }
#pragma unroll
            for (int p = 0; p < 4; p++) {
                uint32_t bd = bbase + (wn*64 + p*16 + lrow)*ASTRIDE + lchunk*16;
                LDMX4(bf[p][0], bf[p][1], bf[p][2], bf[p][3], bd);
            }
#pragma unroll
            for (int ma = 0; ma < 2; ma++)
#pragma unroll
                for (int nn = 0; nn < 8; nn++) {
                    int p = nn >> 1, hi = nn & 1;
                    MMA_BF16(acc[ma][nn], a[ma][0], a[ma][1], a[ma][2], a[ma][3],
                             bf[p][hi], bf[p][2 + hi]);
                }
        }
        if (k0 + 2 < NKIT) load_stage(k0 + 2, (k0 + 2) % GSTAGES);
        CP_COMMIT();                // empty groups keep the accounting uniform
    }

    // ---- fused epilogue ----
    const int group = lane >> 2, qd = lane & 3;
    float lsum = 0.0f;
#pragma unroll
    for (int ma = 0; ma < 2; ma++) {
#pragma unroll
        for (int nn = 0; nn < 8; nn++) {
            int col  = n0 + wn*64 + nn*8 + qd*2;
            int row0 = m0 + wm*32 + ma*16 + group;
#pragma unroll
            for (int h = 0; h < 2; h++) {
                int r = row0 + h*8;
                size_t idx = (size_t)r * DDIM + col;
                float v0 = acc[ma][nn][h*2], v1 = acc[ma][nn][h*2 + 1];
                if (MODE == 0) {
                    float2 bu = *(const float2*)&extra[idx];
                    float2 bs = *(const float2*)&bias[col];
                    __nv_bfloat162 e = __float22bfloat162_rn(
                        make_float2(bu.x - (v0 + bs.x), bu.y - (v1 + bs.y)));
                    *(uint32_t*)&g_err_bf[idx] = *(uint32_t*)&e;
                } else if (MODE == 1) {
                    float2 bs = *(const float2*)&bias[col];
                    float2 ba = *(const float2*)&g_base[idx];
                    *(float2*)&g_rd[idx] = make_float2(v0 + bs.x + ba.x,
                                                       v1 + bs.y + ba.y);
                } else {
                    uint32_t pu = *(const uint32_t*)&g_phid_bf[idx];
                    float2 ph = __bfloat1622float2(*(__nv_bfloat162*)&pu);
                    float2 rd = *(const float2*)&g_rd[idx];
                    float s0 = fmaf(v0, ph.x, rd.x);
                    float s1 = fmaf(v1, ph.y, rd.y);
                    *(float2*)&g_sg[idx] = make_float2(s0, s1);
                    lsum = fmaf(s0, s0, fmaf(s1, s1, lsum));
                }
            }
        }
    }

    if (MODE == 2) {
        __shared__ float red[8];
#pragma unroll
        for (int o = 16; o > 0; o >>= 1) lsum += __shfl_xor_sync(0xffffffff, lsum, o);
        if (lane == 0) red[wid] = lsum;
        __syncthreads();
        if (tid == 0) {
            float s = 0.0f;
#pragma unroll
            for (int w = 0; w < 8; w++) s += red[w];
            atomicAdd(&g_norm2, (double)s);
        }
    }
}

// ------------------------------ finalize ----------------------------------
__global__ __launch_bounds__(256) void finalize(const float* __restrict__ x,
                                                const int* __restrict__ step,
                                                float* __restrict__ out)
{
    float c = 0.5f * (0.8f / (1.0f + 0.1f * (float)(*step)));
    float n = c * (float)sqrt(g_norm2);
    float scale = (n > 1.0f) ? (c / (n + 1e-8f)) : c;

    int i4 = blockIdx.x * blockDim.x + threadIdx.x;
    float4 xv = *(const float4*)(x + (size_t)i4 * 4);
    float4 sv = *(const float4*)(g_sg + (size_t)i4 * 4);
    float4 o;
    o.x = fminf(5.0f, fmaxf(-5.0f, fmaf(scale, sv.x, xv.x)));
    o.y = fminf(5.0f, fmaxf(-5.0f, fmaf(scale, sv.y, xv.y)));
    o.z = fminf(5.0f, fmaxf(-5.0f, fmaf(scale, sv.z, xv.z)));
    o.w = fminf(5.0f, fmaxf(-5.0f, fmaf(scale, sv.w, xv.w)));
    *(float4*)(out + (size_t)i4 * 4) = o;
}

// ---------------------------------------------------------------------------
extern "C" void kernel_launch(void* const* d_in, const int* in_sizes, int n_in,
                              void* d_out, int out_size)
{
    const float* bottom_up = (const float*)d_in[0];
    const float* td        = (const float*)d_in[1];
    const float* x         = (const float*)d_in[2];
    const float* V         = (const float*)d_in[3];
    const float* b_in      = (const float*)d_in[4];
    const float* W         = (const float*)d_in[5];
    const float* b_out     = (const float*)d_in[6];
    const float* L         = (const float*)d_in[7];
    const float* Lm        = (const float*)d_in[8];
    const int*   step      = (const int*)  d_in[9];
    float* out = (float*)d_out;

    cudaFuncSetAttribute(gemm_hmma<0>, cudaFuncAttributeMaxDynamicSharedMemorySize, GSMEM);
    cudaFuncSetAttribute(gemm_hmma<1>, cudaFuncAttributeMaxDynamicSharedMemorySize, GSMEM);
    cudaFuncSetAttribute(gemm_hmma<2>, cudaFuncAttributeMaxDynamicSharedMemorySize, GSMEM);

    build_sc<<<2, 256>>>(L, Lm);
    transpose_prep<<<dim3(16, 16), dim3(32, 8)>>>(W, V);
    convert_bu<<<NTOT / (256 * 8), 256>>>((const float4*)bottom_up);
    rowprep<<<BDIM, 512>>>(x, td);

    dim3 grid(DDIM / BN, BDIM / BM);   // (4, 128)
    gemm_hmma<1><<<grid, 256, GSMEM>>>(b_in,  nullptr);     // rd = bu@V + b_in + base
    gemm_hmma<0><<<grid, 256, GSMEM>>>(b_out, bottom_up);   // err = bu - (phi@W + b_out)
    gemm_hmma<2><<<grid, 256, GSMEM>>>(nullptr, nullptr);   // sg + ||sg||^2

    finalize<<<NTOT / 4 / 256, 256>>>(x, step, out);
}

// round 8
// speedup vs baseline: 1.6771x; 1.6771x over previous
#include <cuda_runtime.h>
#include <cuda_bf16.h>
#include <math.h>
#include <stdint.h>

// ---------------------------------------------------------------------------
// PredictiveColumn on GB300 via mma.sync bf16.
//   build_sc       : transposed 7-tap band g_Sct[d][n] + zero norm
//   transpose_prep : bf16 W / W^T / V^T via tiled smem transpose
//   convert_bu     : bottom_up fp32 -> bf16
//   rowprep        : WARP-PER-ROW exact kWTA (register bitplanes + REDUX),
//                    phi(bf16), phi'(bf16), base(bf16)
//   gemm<1>        : rd  = bu @ V + b_in + base  -> bf16    (B = V^T)
//   gemm<0>        : err = bu - (phi @ W + b_out) -> bf16   (B = W^T)
//   gemm<2>        : sg  = (err @ W^T)*phi' + rd -> bf16 ; ||sg||^2  (B = W)
//   finalize       : out = clip(x + scale*sg, -5, 5)
// ---------------------------------------------------------------------------

#define BDIM 16384
#define DDIM 512
#define KWTA 128
#define NTOT (BDIM*DDIM)

__device__ __nv_bfloat16 g_bu_bf  [NTOT];
__device__ __nv_bfloat16 g_phi_bf [NTOT];
__device__ __nv_bfloat16 g_err_bf [NTOT];
__device__ __nv_bfloat16 g_phid_bf[NTOT];
__device__ __nv_bfloat16 g_base_bf[NTOT];
__device__ __nv_bfloat16 g_rd_bf  [NTOT];
__device__ __nv_bfloat16 g_sg_bf  [NTOT];
__device__ __nv_bfloat16 g_W_bf [DDIM*DDIM];
__device__ __nv_bfloat16 g_Wt_bf[DDIM*DDIM];
__device__ __nv_bfloat16 g_Vt_bf[DDIM*DDIM];
__device__ float  g_Sct[8*DDIM];     // [d][n], d=7 row is zero
__device__ double g_norm2;

// ------------------------------ helpers -----------------------------------
__device__ __forceinline__ uint32_t smem_to_u32(const void* p) {
    uint32_t a;
    asm("{ .reg .u64 t; cvta.to.shared.u64 t, %1; cvt.u32.u64 %0, t; }" : "=r"(a) : "l"(p));
    return a;
}
__device__ __forceinline__ void cpa16(uint32_t dst, const void* src) {
    asm volatile("cp.async.cg.shared.global [%0], [%1], 16;" :: "r"(dst), "l"(src));
}
#define CP_COMMIT() asm volatile("cp.async.commit_group;" ::: "memory")
#define CP_WAIT1()  asm volatile("cp.async.wait_group 1;" ::: "memory")

#define LDMX4(r0, r1, r2, r3, addr) \
    asm volatile("ldmatrix.sync.aligned.m8n8.x4.shared.b16 {%0,%1,%2,%3}, [%4];" \
                 : "=r"(r0), "=r"(r1), "=r"(r2), "=r"(r3) : "r"(addr))

#define MMA_BF16(c, a0, a1, a2, a3, b0, b1) \
    asm volatile("mma.sync.aligned.m16n8k16.row.col.f32.bf16.bf16.f32 " \
                 "{%0,%1,%2,%3}, {%4,%5,%6,%7}, {%8,%9}, {%0,%1,%2,%3};" \
                 : "+f"((c)[0]), "+f"((c)[1]), "+f"((c)[2]), "+f"((c)[3]) \
                 : "r"(a0), "r"(a1), "r"(a2), "r"(a3), "r"(b0), "r"(b1))

// ------------------------------ prep kernels ------------------------------
__global__ __launch_bounds__(256) void build_sc(const float* __restrict__ L,
                                                const float* __restrict__ Lm)
{
    int n = blockIdx.x * 256 + threadIdx.x;
    if (n == 0) g_norm2 = 0.0;
    if (n >= DDIM) return;
#pragma unroll
    for (int d = 0; d < 7; d++) {
        int j = n - 3 + d;
        float v = 0.0f;
        if (j >= 0 && j < DDIM) v = L[(size_t)j*DDIM + n] * Lm[(size_t)j*DDIM + n];
        g_Sct[d*DDIM + n] = v;
    }
    g_Sct[7*DDIM + n] = 0.0f;
}

// tiled transpose: W -> W_bf, Wt_bf ; V -> Vt_bf. 32x32 tiles, block (32,8).
__global__ __launch_bounds__(256) void transpose_prep(const float* __restrict__ W,
                                                      const float* __restrict__ V)
{
    __shared__ float tw[32][33];
    __shared__ float tv[32][33];
    const int tx = threadIdx.x, ty = threadIdx.y;
    const int x0 = blockIdx.x * 32, y0 = blockIdx.y * 32;
#pragma unroll
    for (int r = 0; r < 4; r++) {
        int row = y0 + ty + r*8;
        float w = W[(size_t)row*DDIM + x0 + tx];
        float v = V[(size_t)row*DDIM + x0 + tx];
        tw[ty + r*8][tx] = w;
        tv[ty + r*8][tx] = v;
        g_W_bf[(size_t)row*DDIM + x0 + tx] = __float2bfloat16(w);
    }
    __syncthreads();
#pragma unroll
    for (int r = 0; r < 4; r++) {
        int row = x0 + ty + r*8;
        g_Wt_bf[(size_t)row*DDIM + y0 + tx] = __float2bfloat16(tw[tx][ty + r*8]);
        g_Vt_bf[(size_t)row*DDIM + y0 + tx] = __float2bfloat16(tv[tx][ty + r*8]);
    }
}

__global__ __launch_bounds__(256) void convert_bu(const float4* __restrict__ src)
{
    int i = blockIdx.x * 256 + threadIdx.x;          // 8 floats per thread
    float4 a = src[i*2], b = src[i*2+1];
    __nv_bfloat162 p0 = __float22bfloat162_rn(make_float2(a.x, a.y));
    __nv_bfloat162 p1 = __float22bfloat162_rn(make_float2(a.z, a.w));
    __nv_bfloat162 p2 = __float22bfloat162_rn(make_float2(b.x, b.y));
    __nv_bfloat162 p3 = __float22bfloat162_rn(make_float2(b.z, b.w));
    uint4 o;
    o.x = *(uint32_t*)&p0; o.y = *(uint32_t*)&p1; o.z = *(uint32_t*)&p2; o.w = *(uint32_t*)&p3;
    *(uint4*)(&g_bu_bf[(size_t)i*8]) = o;
}

// ------------------------------ rowprep -----------------------------------
// One WARP per row; 16 values/lane, strided i = lane + 32*j.
// Exact k-th-largest key via 32 register bitplane passes + REDUX; tie
// resolution lowest-index-first via per-j ballots. No block barriers in the
// selection path.
__global__ __launch_bounds__(256) void rowprep(const float* __restrict__ x,
                                               const float* __restrict__ td)
{
    __shared__ float sSc[8*DDIM];       // taps, transposed [d][i]
    __shared__ float sphi[8][520];      // per-warp phi row, 3-guard each side

    const int tid = threadIdx.x, wid = tid >> 5, lane = tid & 31;
    const unsigned FULL = 0xffffffffu;

    for (int q = tid; q < 8*DDIM/4; q += 256)
        ((float4*)sSc)[q] = ((const float4*)g_Sct)[q];
    if (lane < 3) sphi[wid][lane] = 0.0f;
    if (lane < 5) sphi[wid][515 + lane] = 0.0f;
    __syncthreads();

    const size_t rb = ((size_t)blockIdx.x * 8 + wid) * DDIM;

    float f[16]; uint32_t u[16], d[16];
#pragma unroll
    for (int j = 0; j < 16; j++) {
        f[j] = x[rb + lane + 32*j];
        uint32_t b = __float_as_uint(f[j]);
        u[j] = (b & 0x80000000u) ? ~b : (b | 0x80000000u);   // order-preserving
        d[j] = u[j];
    }

    // ---- bitplane select of the KWTA-th largest key ----
    uint32_t pfx = 0; int rem = KWTA;
#pragma unroll 1
    for (int bit = 31; bit >= 0; --bit) {
        int cl = 0;
#pragma unroll
        for (int j = 0; j < 16; j++) cl += ((d[j] >> bit) == 1u);
        int tot = __reduce_add_sync(FULL, cl);
        if (tot >= rem) {
            uint32_t bm = 1u << bit;
            pfx |= bm;
#pragma unroll
            for (int j = 0; j < 16; j++) d[j] ^= bm;
        } else {
            rem -= tot;
        }
    }

    int cgt = 0;
#pragma unroll
    for (int j = 0; j < 16; j++) cgt += (u[j] > pfx);
    const int need = KWTA - __reduce_add_sync(FULL, cgt);

    // ---- mask + phi/phi' (ties ranked by global index ascending) ----
    const float inv_sqrt2   = 0.7071067811865476f;
    const float inv_sqrt2pi = 0.3989422804014327f;
    int eq_before = 0;
#pragma unroll
    for (int j = 0; j < 16; j++) {
        bool eqj = (u[j] == pfx);
        unsigned bal = __ballot_sync(FULL, eqj);
        bool m = (u[j] > pfx) ||
                 (eqj && (eq_before + __popc(bal & ((1u << lane) - 1u))) < need);
        eq_before += __popc(bal);

        float v = f[j];
        float cdf = 0.5f * (1.0f + erff(v * inv_sqrt2));
        float pdf = expf(-0.5f * v * v) * inv_sqrt2pi;
        float ph = m ? v * cdf : 0.0f;
        float pd = m ? (cdf + v * pdf) : 0.0f;
        int i = lane + 32*j;
        sphi[wid][3 + i] = ph;
        g_phi_bf [rb + i] = __float2bfloat16(ph);
        g_phid_bf[rb + i] = __float2bfloat16(pd);
    }
    __syncwarp();

    // ---- lateral stencil + base ----
#pragma unroll
    for (int j = 0; j < 16; j++) {
        int i = lane + 32*j;
        float lat = 0.0f;
#pragma unroll
        for (int d2 = 0; d2 < 7; d2++)
            lat = fmaf(sphi[wid][i + d2], sSc[d2*DDIM + i], lat);   // [3+i-3+d2]
        float v = f[j];
        float sgn = (v > 0.0f) ? 1.0f : ((v < 0.0f) ? -1.0f : 0.0f);
        float bse = 0.3f*lat + 3.0f*td[rb + i] - 4.0f*v - 1e-6f*sgn;
        g_base_bf[rb + i] = __float2bfloat16(bse);
    }
}

// ------------------------------ HMMA GEMM ---------------------------------
// BM=128, BN=128, BK=32; 256 threads = 8 warps (4m x 2n), warp tile 32x64.
// SMEM rows padded to 80B. 2-stage cp.async double buffer (R6-proven).
#define BM 128
#define BN 128
#define BK 32
#define NKIT (DDIM / BK)     // 16
#define ASTRIDE 80
#define B_OFF   (BM * ASTRIDE)             // 10240
#define BUFBYTES ((BM + BN) * ASTRIDE)     // 20480

template<int MODE>
__global__ __launch_bounds__(256)
void gemm_hmma(const float* __restrict__ bias, const float* __restrict__ extra)
{
    __shared__ char smem[2 * BUFBYTES];
    const uint32_t sbase = smem_to_u32(smem);

    const int tid  = threadIdx.x;
    const int wid  = tid >> 5, lane = tid & 31;
    const int wm   = wid & 3;          // m offset 32*wm
    const int wn   = wid >> 2;         // n offset 64*wn
    const int m0   = blockIdx.y * BM;
    const int n0   = blockIdx.x * BN;

    const __nv_bfloat16* A  = (MODE == 1) ? g_bu_bf : (MODE == 0 ? g_phi_bf : g_err_bf);
    const __nv_bfloat16* Bt = (MODE == 1) ? g_Vt_bf : (MODE == 0 ? g_Wt_bf : g_W_bf);

    float acc[2][8][4];
#pragma unroll
    for (int i = 0; i < 2; i++)
#pragma unroll
        for (int j = 0; j < 8; j++)
#pragma unroll
            for (int q = 0; q < 4; q++) acc[i][j][q] = 0.0f;

    auto load_stage = [&](int k0, int buf) {
#pragma unroll
        for (int i = 0; i < 2; i++) {
            int ch = tid * 2 + i;            // 0..511
            int r = ch >> 2, c = ch & 3;
            cpa16(sbase + buf*BUFBYTES + r*ASTRIDE + c*16,
                  (const char*)A + ((size_t)(m0 + r) * DDIM + k0*BK + c*8) * 2);
            cpa16(sbase + buf*BUFBYTES + B_OFF + r*ASTRIDE + c*16,
                  (const char*)Bt + ((size_t)(n0 + r) * DDIM + k0*BK + c*8) * 2);
        }
    };

    load_stage(0, 0);
    CP_COMMIT();

#pragma unroll 1
    for (int k0 = 0; k0 < NKIT; k0++) {
        const int buf = k0 & 1;
        if (k0 + 1 < NKIT) load_stage(k0 + 1, buf ^ 1);
        CP_COMMIT();
        CP_WAIT1();
        __syncthreads();

        const uint32_t abase = sbase + buf*BUFBYTES;
        const uint32_t bbase = abase + B_OFF;
        const int lrow = lane & 15;
#pragma unroll
        for (int ks = 0; ks < 2; ks++) {
            const int lchunk = ks*2 + (lane >> 4);
            uint32_t a[2][4], bf[4][4];
#pragma unroll
            for (int ma = 0; ma < 2; ma++) {
                uint32_t ad = abase + (wm*32 + ma*16 + lrow)*ASTRIDE + lchunk*16;
                LDMX4(a[ma][0], a[ma][1], a[ma][2], a[ma][3], ad);
            }
#pragma unroll
            for (int p = 0; p < 4; p++) {
                uint32_t bd = bbase + (wn*64 + p*16 + lrow)*ASTRIDE + lchunk*16;
                LDMX4(bf[p][0], bf[p][1], bf[p][2], bf[p][3], bd);
            }
#pragma unroll
            for (int ma = 0; ma < 2; ma++)
#pragma unroll
                for (int nn = 0; nn < 8; nn++) {
                    int p = nn >> 1, hi = nn & 1;
                    MMA_BF16(acc[ma][nn], a[ma][0], a[ma][1], a[ma][2], a[ma][3],
                             bf[p][hi], bf[p][2 + hi]);
                }
        }
        __syncthreads();
    }

    // ---- fused epilogue (bf16 streams) ----
    const int group = lane >> 2, qd = lane & 3;
    float lsum = 0.0f;
#pragma unroll
    for (int ma = 0; ma < 2; ma++) {
#pragma unroll
        for (int nn = 0; nn < 8; nn++) {
            int col  = n0 + wn*64 + nn*8 + qd*2;
            int row0 = m0 + wm*32 + ma*16 + group;
#pragma unroll
            for (int h = 0; h < 2; h++) {
                int r = row0 + h*8;
                size_t idx = (size_t)r * DDIM + col;
                float v0 = acc[ma][nn][h*2], v1 = acc[ma][nn][h*2 + 1];
                if (MODE == 0) {
                    float2 bu = *(const float2*)&extra[idx];
                    float2 bs = *(const float2*)&bias[col];
                    __nv_bfloat162 e = __float22bfloat162_rn(
                        make_float2(bu.x - (v0 + bs.x), bu.y - (v1 + bs.y)));
                    *(uint32_t*)&g_err_bf[idx] = *(uint32_t*)&e;
                } else if (MODE == 1) {
                    float2 bs = *(const float2*)&bias[col];
                    uint32_t bb = *(const uint32_t*)&g_base_bf[idx];
                    float2 ba = __bfloat1622float2(*(__nv_bfloat162*)&bb);
                    __nv_bfloat162 o = __float22bfloat162_rn(
                        make_float2(v0 + bs.x + ba.x, v1 + bs.y + ba.y));
                    *(uint32_t*)&g_rd_bf[idx] = *(uint32_t*)&o;
                } else {
                    uint32_t pu = *(const uint32_t*)&g_phid_bf[idx];
                    uint32_t ru = *(const uint32_t*)&g_rd_bf[idx];
                    float2 ph = __bfloat1622float2(*(__nv_bfloat162*)&pu);
                    float2 rd = __bfloat1622float2(*(__nv_bfloat162*)&ru);
                    float s0 = fmaf(v0, ph.x, rd.x);
                    float s1 = fmaf(v1, ph.y, rd.y);
                    __nv_bfloat162 o = __float22bfloat162_rn(make_float2(s0, s1));
                    *(uint32_t*)&g_sg_bf[idx] = *(uint32_t*)&o;
                    lsum = fmaf(s0, s0, fmaf(s1, s1, lsum));
                }
            }
        }
    }

    if (MODE == 2) {
        __shared__ float red[8];
#pragma unroll
        for (int o = 16; o > 0; o >>= 1) lsum += __shfl_xor_sync(0xffffffff, lsum, o);
        if (lane == 0) red[wid] = lsum;
        __syncthreads();
        if (tid == 0) {
            float s = 0.0f;
#pragma unroll
            for (int w = 0; w < 8; w++) s += red[w];
            atomicAdd(&g_norm2, (double)s);
        }
    }
}

// ------------------------------ finalize ----------------------------------
// 8 elements per thread: out = clip(x + scale*sg, -5, 5)
__global__ __launch_bounds__(256) void finalize(const float* __restrict__ x,
                                                const int* __restrict__ step,
                                                float* __restrict__ out)
{
    float c = 0.5f * (0.8f / (1.0f + 0.1f * (float)(*step)));
    float n = c * (float)sqrt(g_norm2);
    float scale = (n > 1.0f) ? (c / (n + 1e-8f)) : c;

    size_t i8 = (size_t)(blockIdx.x * blockDim.x + threadIdx.x) * 8;
    uint4 su = *(const uint4*)&g_sg_bf[i8];
    const uint32_t* sp = (const uint32_t*)&su;
#pragma unroll
    for (int h = 0; h < 2; h++) {
        float4 xv = *(const float4*)(x + i8 + h*4);
        float2 sa = __bfloat1622float2(*(__nv_bfloat162*)&sp[h*2]);
        float2 sb = __bfloat1622float2(*(__nv_bfloat162*)&sp[h*2 + 1]);
        float4 o;
        o.x = fminf(5.0f, fmaxf(-5.0f, fmaf(scale, sa.x, xv.x)));
        o.y = fminf(5.0f, fmaxf(-5.0f, fmaf(scale, sa.y, xv.y)));
        o.z = fminf(5.0f, fmaxf(-5.0f, fmaf(scale, sb.x, xv.z)));
        o.w = fminf(5.0f, fmaxf(-5.0f, fmaf(scale, sb.y, xv.w)));
        *(float4*)(out + i8 + h*4) = o;
    }
}

// ---------------------------------------------------------------------------
extern "C" void kernel_launch(void* const* d_in, const int* in_sizes, int n_in,
                              void* d_out, int out_size)
{
    const float* bottom_up = (const float*)d_in[0];
    const float* td        = (const float*)d_in[1];
    const float* x         = (const float*)d_in[2];
    const float* V         = (const float*)d_in[3];
    const float* b_in      = (const float*)d_in[4];
    const float* W         = (const float*)d_in[5];
    const float* b_out     = (const float*)d_in[6];
    const float* L         = (const float*)d_in[7];
    const float* Lm        = (const float*)d_in[8];
    const int*   step      = (const int*)  d_in[9];
    float* out = (float*)d_out;

    build_sc<<<2, 256>>>(L, Lm);
    transpose_prep<<<dim3(16, 16), dim3(32, 8)>>>(W, V);
    convert_bu<<<NTOT / (256 * 8), 256>>>((const float4*)bottom_up);
    rowprep<<<BDIM / 8, 256>>>(x, td);

    dim3 grid(DDIM / BN, BDIM / BM);   // (4, 128)
    gemm_hmma<1><<<grid, 256>>>(b_in,  nullptr);     // rd = bu@V + b_in + base
    gemm_hmma<0><<<grid, 256>>>(b_out, bottom_up);   // err = bu - (phi@W + b_out)
    gemm_hmma<2><<<grid, 256>>>(nullptr, nullptr);   // sg + ||sg||^2

    finalize<<<NTOT / 8 / 256, 256>>>(x, step, out);
}

// round 9
// speedup vs baseline: 1.6917x; 1.0087x over previous
#include <cuda_runtime.h>
#include <cuda_bf16.h>
#include <math.h>
#include <stdint.h>

// ---------------------------------------------------------------------------
// PredictiveColumn on GB300 via mma.sync bf16.
//   build_sc       : transposed 7-tap band g_Sct[d][n] + zero norm
//   transpose_prep : bf16 W / W^T / V^T via tiled smem transpose
//   convert_bu     : bottom_up fp32 -> bf16
//   rowprep        : WARP-PER-ROW exact kWTA (register bitplanes + REDUX),
//                    phi(bf16), phi'(bf16), base(bf16)
//   gemm<1>        : rd  = bu @ V + b_in + base  -> bf16    (B = V^T)
//   gemm<0>        : err = bu - (phi @ W + b_out) -> bf16   (B = W^T)
//   gemm<2>        : sg  = (err @ W^T)*phi' + rd -> bf16 ; ||sg||^2  (B = W)
//   finalize       : out = clip(x + scale*sg, -5, 5)
// GEMM: BM=256 x BN=128, 512 threads, 2-stage cp.async (LDGSTS-issue-bound:
// bigger tile cuts staged bytes/FLOP vs R8's 128x128).
// ---------------------------------------------------------------------------

#define BDIM 16384
#define DDIM 512
#define KWTA 128
#define NTOT (BDIM*DDIM)

__device__ __nv_bfloat16 g_bu_bf  [NTOT];
__device__ __nv_bfloat16 g_phi_bf [NTOT];
__device__ __nv_bfloat16 g_err_bf [NTOT];
__device__ __nv_bfloat16 g_phid_bf[NTOT];
__device__ __nv_bfloat16 g_base_bf[NTOT];
__device__ __nv_bfloat16 g_rd_bf  [NTOT];
__device__ __nv_bfloat16 g_sg_bf  [NTOT];
__device__ __nv_bfloat16 g_W_bf [DDIM*DDIM];
__device__ __nv_bfloat16 g_Wt_bf[DDIM*DDIM];
__device__ __nv_bfloat16 g_Vt_bf[DDIM*DDIM];
__device__ float  g_Sct[8*DDIM];     // [d][n], d=7 row is zero
__device__ double g_norm2;

// ------------------------------ helpers -----------------------------------
__device__ __forceinline__ uint32_t smem_to_u32(const void* p) {
    uint32_t a;
    asm("{ .reg .u64 t; cvta.to.shared.u64 t, %1; cvt.u32.u64 %0, t; }" : "=r"(a) : "l"(p));
    return a;
}
__device__ __forceinline__ void cpa16(uint32_t dst, const void* src) {
    asm volatile("cp.async.cg.shared.global [%0], [%1], 16;" :: "r"(dst), "l"(src));
}
#define CP_COMMIT() asm volatile("cp.async.commit_group;" ::: "memory")
#define CP_WAIT1()  asm volatile("cp.async.wait_group 1;" ::: "memory")

#define LDMX4(r0, r1, r2, r3, addr) \
    asm volatile("ldmatrix.sync.aligned.m8n8.x4.shared.b16 {%0,%1,%2,%3}, [%4];" \
                 : "=r"(r0), "=r"(r1), "=r"(r2), "=r"(r3) : "r"(addr))

#define MMA_BF16(c, a0, a1, a2, a3, b0, b1) \
    asm volatile("mma.sync.aligned.m16n8k16.row.col.f32.bf16.bf16.f32 " \
                 "{%0,%1,%2,%3}, {%4,%5,%6,%7}, {%8,%9}, {%0,%1,%2,%3};" \
                 : "+f"((c)[0]), "+f"((c)[1]), "+f"((c)[2]), "+f"((c)[3]) \
                 : "r"(a0), "r"(a1), "r"(a2), "r"(a3), "r"(b0), "r"(b1))

// ------------------------------ prep kernels ------------------------------
__global__ __launch_bounds__(256) void build_sc(const float* __restrict__ L,
                                                const float* __restrict__ Lm)
{
    int n = blockIdx.x * 256 + threadIdx.x;
    if (n == 0) g_norm2 = 0.0;
    if (n >= DDIM) return;
#pragma unroll
    for (int d = 0; d < 7; d++) {
        int j = n - 3 + d;
        float v = 0.0f;
        if (j >= 0 && j < DDIM) v = L[(size_t)j*DDIM + n] * Lm[(size_t)j*DDIM + n];
        g_Sct[d*DDIM + n] = v;
    }
    g_Sct[7*DDIM + n] = 0.0f;
}

// tiled transpose: W -> W_bf, Wt_bf ; V -> Vt_bf. 32x32 tiles, block (32,8).
__global__ __launch_bounds__(256) void transpose_prep(const float* __restrict__ W,
                                                      const float* __restrict__ V)
{
    __shared__ float tw[32][33];
    __shared__ float tv[32][33];
    const int tx = threadIdx.x, ty = threadIdx.y;
    const int x0 = blockIdx.x * 32, y0 = blockIdx.y * 32;
#pragma unroll
    for (int r = 0; r < 4; r++) {
        int row = y0 + ty + r*8;
        float w = W[(size_t)row*DDIM + x0 + tx];
        float v = V[(size_t)row*DDIM + x0 + tx];
        tw[ty + r*8][tx] = w;
        tv[ty + r*8][tx] = v;
        g_W_bf[(size_t)row*DDIM + x0 + tx] = __float2bfloat16(w);
    }
    __syncthreads();
#pragma unroll
    for (int r = 0; r < 4; r++) {
        int row = x0 + ty + r*8;
        g_Wt_bf[(size_t)row*DDIM + y0 + tx] = __float2bfloat16(tw[tx][ty + r*8]);
        g_Vt_bf[(size_t)row*DDIM + y0 + tx] = __float2bfloat16(tv[tx][ty + r*8]);
    }
}

__global__ __launch_bounds__(256) void convert_bu(const float4* __restrict__ src)
{
    int i = blockIdx.x * 256 + threadIdx.x;          // 8 floats per thread
    float4 a = src[i*2], b = src[i*2+1];
    __nv_bfloat162 p0 = __float22bfloat162_rn(make_float2(a.x, a.y));
    __nv_bfloat162 p1 = __float22bfloat162_rn(make_float2(a.z, a.w));
    __nv_bfloat162 p2 = __float22bfloat162_rn(make_float2(b.x, b.y));
    __nv_bfloat162 p3 = __float22bfloat162_rn(make_float2(b.z, b.w));
    uint4 o;
    o.x = *(uint32_t*)&p0; o.y = *(uint32_t*)&p1; o.z = *(uint32_t*)&p2; o.w = *(uint32_t*)&p3;
    *(uint4*)(&g_bu_bf[(size_t)i*8]) = o;
}

// ------------------------------ rowprep -----------------------------------
// One WARP per row; 16 values/lane, strided i = lane + 32*j.
// Exact k-th-largest key via 32 register bitplane passes + REDUX; tie
// resolution lowest-index-first via per-j ballots.
__global__ __launch_bounds__(256) void rowprep(const float* __restrict__ x,
                                               const float* __restrict__ td)
{
    __shared__ float sSc[8*DDIM];       // taps, transposed [d][i]
    __shared__ float sphi[8][520];      // per-warp phi row, 3-guard each side

    const int tid = threadIdx.x, wid = tid >> 5, lane = tid & 31;
    const unsigned FULL = 0xffffffffu;

    for (int q = tid; q < 8*DDIM/4; q += 256)
        ((float4*)sSc)[q] = ((const float4*)g_Sct)[q];
    if (lane < 3) sphi[wid][lane] = 0.0f;
    if (lane < 5) sphi[wid][515 + lane] = 0.0f;
    __syncthreads();

    const size_t rb = ((size_t)blockIdx.x * 8 + wid) * DDIM;

    float f[16]; uint32_t u[16], d[16];
#pragma unroll
    for (int j = 0; j < 16; j++) {
        f[j] = x[rb + lane + 32*j];
        uint32_t b = __float_as_uint(f[j]);
        u[j] = (b & 0x80000000u) ? ~b : (b | 0x80000000u);   // order-preserving
        d[j] = u[j];
    }

    // ---- bitplane select of the KWTA-th largest key ----
    uint32_t pfx = 0; int rem = KWTA;
#pragma unroll 1
    for (int bit = 31; bit >= 0; --bit) {
        int cl = 0;
#pragma unroll
        for (int j = 0; j < 16; j++) cl += ((d[j] >> bit) == 1u);
        int tot = __reduce_add_sync(FULL, cl);
        if (tot >= rem) {
            uint32_t bm = 1u << bit;
            pfx |= bm;
#pragma unroll
            for (int j = 0; j < 16; j++) d[j] ^= bm;
        } else {
            rem -= tot;
        }
    }

    int cgt = 0;
#pragma unroll
    for (int j = 0; j < 16; j++) cgt += (u[j] > pfx);
    const int need = KWTA - __reduce_add_sync(FULL, cgt);

    // ---- mask + phi/phi' (ties ranked by global index ascending) ----
    const float inv_sqrt2   = 0.7071067811865476f;
    const float inv_sqrt2pi = 0.3989422804014327f;
    int eq_before = 0;
#pragma unroll
    for (int j = 0; j < 16; j++) {
        bool eqj = (u[j] == pfx);
        unsigned bal = __ballot_sync(FULL, eqj);
        bool m = (u[j] > pfx) ||
                 (eqj && (eq_before + __popc(bal & ((1u << lane) - 1u))) < need);
        eq_before += __popc(bal);

        float v = f[j];
        float cdf = 0.5f * (1.0f + erff(v * inv_sqrt2));
        float pdf = expf(-0.5f * v * v) * inv_sqrt2pi;
        float ph = m ? v * cdf : 0.0f;
        float pd = m ? (cdf + v * pdf) : 0.0f;
        int i = lane + 32*j;
        sphi[wid][3 + i] = ph;
        g_phi_bf [rb + i] = __float2bfloat16(ph);
        g_phid_bf[rb + i] = __float2bfloat16(pd);
    }
    __syncwarp();

    // ---- lateral stencil + base ----
#pragma unroll
    for (int j = 0; j < 16; j++) {
        int i = lane + 32*j;
        float lat = 0.0f;
#pragma unroll
        for (int d2 = 0; d2 < 7; d2++)
            lat = fmaf(sphi[wid][i + d2], sSc[d2*DDIM + i], lat);   // [3+i-3+d2]
        float v = f[j];
        float sgn = (v > 0.0f) ? 1.0f : ((v < 0.0f) ? -1.0f : 0.0f);
        float bse = 0.3f*lat + 3.0f*td[rb + i] - 4.0f*v - 1e-6f*sgn;
        g_base_bf[rb + i] = __float2bfloat16(bse);
    }
}

// ------------------------------ HMMA GEMM ---------------------------------
// BM=256, BN=128, BK=32; 512 threads = 16 warps (4m x 4n), warp tile 64x32.
// SMEM rows padded to 80B. 2-stage cp.async double buffer, dynamic smem.
#define BM 256
#define BN 128
#define BK 32
#define NKIT (DDIM / BK)     // 16
#define ASTRIDE 80
#define B_OFF   (BM * ASTRIDE)                 // 20480
#define BUFBYTES ((BM + BN) * ASTRIDE)         // 30720
#define GSMEM (2 * BUFBYTES)                   // 61440

template<int MODE>
__global__ __launch_bounds__(512, 1)
void gemm_hmma(const float* __restrict__ bias)
{
    extern __shared__ char smem[];
    const uint32_t sbase = smem_to_u32(smem);

    const int tid  = threadIdx.x;
    const int wid  = tid >> 5, lane = tid & 31;
    const int wm   = wid & 3;          // m offset 64*wm
    const int wn   = wid >> 2;         // n offset 32*wn
    const int m0   = blockIdx.y * BM;
    const int n0   = blockIdx.x * BN;

    const __nv_bfloat16* A  = (MODE == 1) ? g_bu_bf : (MODE == 0 ? g_phi_bf : g_err_bf);
    const __nv_bfloat16* Bt = (MODE == 1) ? g_Vt_bf : (MODE == 0 ? g_Wt_bf : g_W_bf);

    float acc[4][4][4];
#pragma unroll
    for (int i = 0; i < 4; i++)
#pragma unroll
        for (int j = 0; j < 4; j++)
#pragma unroll
            for (int q = 0; q < 4; q++) acc[i][j][q] = 0.0f;

    // stage = A: 1024 chunks (256 rows x 4), B: 512 chunks -> 3 cpa16/thread
    auto load_stage = [&](int k0, int buf) {
#pragma unroll
        for (int i = 0; i < 2; i++) {          // A chunks
            int ch = tid + i*512;
            int r = ch >> 2, c = ch & 3;
            cpa16(sbase + buf*BUFBYTES + r*ASTRIDE + c*16,
                  (const char*)A + ((size_t)(m0 + r) * DDIM + k0*BK + c*8) * 2);
        }
        {                                       // B chunks
            int r = tid >> 2, c = tid & 3;
            cpa16(sbase + buf*BUFBYTES + B_OFF + r*ASTRIDE + c*16,
                  (const char*)Bt + ((size_t)(n0 + r) * DDIM + k0*BK + c*8) * 2);
        }
    };

    load_stage(0, 0);
    CP_COMMIT();

#pragma unroll 1
    for (int k0 = 0; k0 < NKIT; k0++) {
        const int buf = k0 & 1;
        if (k0 + 1 < NKIT) load_stage(k0 + 1, buf ^ 1);
        CP_COMMIT();
        CP_WAIT1();
        __syncthreads();

        const uint32_t abase = sbase + buf*BUFBYTES;
        const uint32_t bbase = abase + B_OFF;
        const int lrow = lane & 15;
#pragma unroll
        for (int ks = 0; ks < 2; ks++) {
            const int lchunk = ks*2 + (lane >> 4);
            uint32_t a[4][4], bf[2][4];
#pragma unroll
            for (int ma = 0; ma < 4; ma++) {
                uint32_t ad = abase + (wm*64 + ma*16 + lrow)*ASTRIDE + lchunk*16;
                LDMX4(a[ma][0], a[ma][1], a[ma][2], a[ma][3], ad);
            }
#pragma unroll
            for (int p = 0; p < 2; p++) {
                uint32_t bd = bbase + (wn*32 + p*16 + lrow)*ASTRIDE + lchunk*16;
                LDMX4(bf[p][0], bf[p][1], bf[p][2], bf[p][3], bd);
            }
#pragma unroll
            for (int ma = 0; ma < 4; ma++)
#pragma unroll
                for (int nn = 0; nn < 4; nn++) {
                    int p = nn >> 1, hi = nn & 1;
                    MMA_BF16(acc[ma][nn], a[ma][0], a[ma][1], a[ma][2], a[ma][3],
                             bf[p][hi], bf[p][2 + hi]);
                }
        }
        __syncthreads();
    }

    // ---- fused epilogue (bf16 streams) ----
    const int group = lane >> 2, qd = lane & 3;
    float lsum = 0.0f;
#pragma unroll
    for (int ma = 0; ma < 4; ma++) {
#pragma unroll
        for (int nn = 0; nn < 4; nn++) {
            int col  = n0 + wn*32 + nn*8 + qd*2;
            int row0 = m0 + wm*64 + ma*16 + group;
#pragma unroll
            for (int h = 0; h < 2; h++) {
                int r = row0 + h*8;
                size_t idx = (size_t)r * DDIM + col;
                float v0 = acc[ma][nn][h*2], v1 = acc[ma][nn][h*2 + 1];
                if (MODE == 0) {
                    uint32_t bb = *(const uint32_t*)&g_bu_bf[idx];
                    float2 bu = __bfloat1622float2(*(__nv_bfloat162*)&bb);
                    float2 bs = *(const float2*)&bias[col];
                    __nv_bfloat162 e = __float22bfloat162_rn(
                        make_float2(bu.x - (v0 + bs.x), bu.y - (v1 + bs.y)));
                    *(uint32_t*)&g_err_bf[idx] = *(uint32_t*)&e;
                } else if (MODE == 1) {
                    float2 bs = *(const float2*)&bias[col];
                    uint32_t bb = *(const uint32_t*)&g_base_bf[idx];
                    float2 ba = __bfloat1622float2(*(__nv_bfloat162*)&bb);
                    __nv_bfloat162 o = __float22bfloat162_rn(
                        make_float2(v0 + bs.x + ba.x, v1 + bs.y + ba.y));
                    *(uint32_t*)&g_rd_bf[idx] = *(uint32_t*)&o;
                } else {
                    uint32_t pu = *(const uint32_t*)&g_phid_bf[idx];
                    uint32_t ru = *(const uint32_t*)&g_rd_bf[idx];
                    float2 ph = __bfloat1622float2(*(__nv_bfloat162*)&pu);
                    float2 rd = __bfloat1622float2(*(__nv_bfloat162*)&ru);
                    float s0 = fmaf(v0, ph.x, rd.x);
                    float s1 = fmaf(v1, ph.y, rd.y);
                    __nv_bfloat162 o = __float22bfloat162_rn(make_float2(s0, s1));
                    *(uint32_t*)&g_sg_bf[idx] = *(uint32_t*)&o;
                    lsum = fmaf(s0, s0, fmaf(s1, s1, lsum));
                }
            }
        }
    }

    if (MODE == 2) {
        __shared__ float red[16];
#pragma unroll
        for (int o = 16; o > 0; o >>= 1) lsum += __shfl_xor_sync(0xffffffff, lsum, o);
        if (lane == 0) red[wid] = lsum;
        __syncthreads();
        if (tid == 0) {
            float s = 0.0f;
#pragma unroll
            for (int w = 0; w < 16; w++) s += red[w];
            atomicAdd(&g_norm2, (double)s);
        }
    }
}

// ------------------------------ finalize ----------------------------------
// 8 elements per thread: out = clip(x + scale*sg, -5, 5)
__global__ __launch_bounds__(256) void finalize(const float* __restrict__ x,
                                                const int* __restrict__ step,
                                                float* __restrict__ out)
{
    float c = 0.5f * (0.8f / (1.0f + 0.1f * (float)(*step)));
    float n = c * (float)sqrt(g_norm2);
    float scale = (n > 1.0f) ? (c / (n + 1e-8f)) : c;

    size_t i8 = (size_t)(blockIdx.x * blockDim.x + threadIdx.x) * 8;
    uint4 su = *(const uint4*)&g_sg_bf[i8];
    const uint32_t* sp = (const uint32_t*)&su;
#pragma unroll
    for (int h = 0; h < 2; h++) {
        float4 xv = *(const float4*)(x + i8 + h*4);
        float2 sa = __bfloat1622float2(*(__nv_bfloat162*)&sp[h*2]);
        float2 sb = __bfloat1622float2(*(__nv_bfloat162*)&sp[h*2 + 1]);
        float4 o;
        o.x = fminf(5.0f, fmaxf(-5.0f, fmaf(scale, sa.x, xv.x)));
        o.y = fminf(5.0f, fmaxf(-5.0f, fmaf(scale, sa.y, xv.y)));
        o.z = fminf(5.0f, fmaxf(-5.0f, fmaf(scale, sb.x, xv.z)));
        o.w = fminf(5.0f, fmaxf(-5.0f, fmaf(scale, sb.y, xv.w)));
        *(float4*)(out + i8 + h*4) = o;
    }
}

// ---------------------------------------------------------------------------
extern "C" void kernel_launch(void* const* d_in, const int* in_sizes, int n_in,
                              void* d_out, int out_size)
{
    const float* bottom_up = (const float*)d_in[0];
    const float* td        = (const float*)d_in[1];
    const float* x         = (const float*)d_in[2];
    const float* V         = (const float*)d_in[3];
    const float* b_in      = (const float*)d_in[4];
    const float* W         = (const float*)d_in[5];
    const float* b_out     = (const float*)d_in[6];
    const float* L         = (const float*)d_in[7];
    const float* Lm        = (const float*)d_in[8];
    const int*   step      = (const int*)  d_in[9];
    float* out = (float*)d_out;

    cudaFuncSetAttribute(gemm_hmma<0>, cudaFuncAttributeMaxDynamicSharedMemorySize, GSMEM);
    cudaFuncSetAttribute(gemm_hmma<1>, cudaFuncAttributeMaxDynamicSharedMemorySize, GSMEM);
    cudaFuncSetAttribute(gemm_hmma<2>, cudaFuncAttributeMaxDynamicSharedMemorySize, GSMEM);

    build_sc<<<2, 256>>>(L, Lm);
    transpose_prep<<<dim3(16, 16), dim3(32, 8)>>>(W, V);
    convert_bu<<<NTOT / (256 * 8), 256>>>((const float4*)bottom_up);
    rowprep<<<BDIM / 8, 256>>>(x, td);

    dim3 grid(DDIM / BN, BDIM / BM);   // (4, 64)
    gemm_hmma<1><<<grid, 512, GSMEM>>>(b_in);    // rd = bu@V + b_in + base
    gemm_hmma<0><<<grid, 512, GSMEM>>>(b_out);   // err = bu - (phi@W + b_out)
    gemm_hmma<2><<<grid, 512, GSMEM>>>(nullptr); // sg + ||sg||^2

    finalize<<<NTOT / 8 / 256, 256>>>(x, step, out);
}

// round 10
// speedup vs baseline: 1.8517x; 1.0946x over previous
#include <cuda_runtime.h>
#include <cuda_bf16.h>
#include <math.h>
#include <stdint.h>

// ---------------------------------------------------------------------------
// PredictiveColumn on GB300 via mma.sync bf16.
//   build_sc       : transposed 7-tap band g_Sct[d][n] + zero norm
//   transpose_prep : bf16 W / W^T / V^T via tiled smem transpose
//   rowprep        : WARP-PER-ROW exact kWTA (register bitplanes + REDUX),
//                    phi(bf16), phi'(bf16), base(bf16), bu fp32->bf16
//   gemm01 (z=0)   : rd  = bu @ V + b_in + base  -> bf16    (B = V^T)
//   gemm01 (z=1)   : err = bu - (phi @ W + b_out) -> bf16   (B = W^T)
//   gemm2          : sg  = (err @ W^T)*phi' + rd -> bf16 ; ||sg||^2  (B = W)
//   finalize       : out = clip(x + scale*sg, -5, 5)
// GEMM: 128x128 tile, 256 thr, 4-stage cp.async, 1 barrier/iter, 2 blocks/SM.
// ---------------------------------------------------------------------------

#define BDIM 16384
#define DDIM 512
#define KWTA 128
#define NTOT (BDIM*DDIM)

__device__ __nv_bfloat16 g_bu_bf  [NTOT];
__device__ __nv_bfloat16 g_phi_bf [NTOT];
__device__ __nv_bfloat16 g_err_bf [NTOT];
__device__ __nv_bfloat16 g_phid_bf[NTOT];
__device__ __nv_bfloat16 g_base_bf[NTOT];
__device__ __nv_bfloat16 g_rd_bf  [NTOT];
__device__ __nv_bfloat16 g_sg_bf  [NTOT];
__device__ __nv_bfloat16 g_W_bf [DDIM*DDIM];
__device__ __nv_bfloat16 g_Wt_bf[DDIM*DDIM];
__device__ __nv_bfloat16 g_Vt_bf[DDIM*DDIM];
__device__ float  g_Sct[8*DDIM];     // [d][n], d=7 row is zero
__device__ double g_norm2;

// ------------------------------ helpers -----------------------------------
__device__ __forceinline__ uint32_t smem_to_u32(const void* p) {
    uint32_t a;
    asm("{ .reg .u64 t; cvta.to.shared.u64 t, %1; cvt.u32.u64 %0, t; }" : "=r"(a) : "l"(p));
    return a;
}
__device__ __forceinline__ void cpa16(uint32_t dst, const void* src) {
    asm volatile("cp.async.cg.shared.global [%0], [%1], 16;" :: "r"(dst), "l"(src));
}
#define CP_COMMIT() asm volatile("cp.async.commit_group;" ::: "memory")
#define CP_WAIT2()  asm volatile("cp.async.wait_group 2;" ::: "memory")

#define LDMX4(r0, r1, r2, r3, addr) \
    asm volatile("ldmatrix.sync.aligned.m8n8.x4.shared.b16 {%0,%1,%2,%3}, [%4];" \
                 : "=r"(r0), "=r"(r1), "=r"(r2), "=r"(r3) : "r"(addr))

#define MMA_BF16(c, a0, a1, a2, a3, b0, b1) \
    asm volatile("mma.sync.aligned.m16n8k16.row.col.f32.bf16.bf16.f32 " \
                 "{%0,%1,%2,%3}, {%4,%5,%6,%7}, {%8,%9}, {%0,%1,%2,%3};" \
                 : "+f"((c)[0]), "+f"((c)[1]), "+f"((c)[2]), "+f"((c)[3]) \
                 : "r"(a0), "r"(a1), "r"(a2), "r"(a3), "r"(b0), "r"(b1))

// ------------------------------ prep kernels ------------------------------
__global__ __launch_bounds__(256) void build_sc(const float* __restrict__ L,
                                                const float* __restrict__ Lm)
{
    int n = blockIdx.x * 256 + threadIdx.x;
    if (n == 0) g_norm2 = 0.0;
    if (n >= DDIM) return;
#pragma unroll
    for (int d = 0; d < 7; d++) {
        int j = n - 3 + d;
        float v = 0.0f;
        if (j >= 0 && j < DDIM) v = L[(size_t)j*DDIM + n] * Lm[(size_t)j*DDIM + n];
        g_Sct[d*DDIM + n] = v;
    }
    g_Sct[7*DDIM + n] = 0.0f;
}

// tiled transpose: W -> W_bf, Wt_bf ; V -> Vt_bf. 32x32 tiles, block (32,8).
__global__ __launch_bounds__(256) void transpose_prep(const float* __restrict__ W,
                                                      const float* __restrict__ V)
{
    __shared__ float tw[32][33];
    __shared__ float tv[32][33];
    const int tx = threadIdx.x, ty = threadIdx.y;
    const int x0 = blockIdx.x * 32, y0 = blockIdx.y * 32;
#pragma unroll
    for (int r = 0; r < 4; r++) {
        int row = y0 + ty + r*8;
        float w = W[(size_t)row*DDIM + x0 + tx];
        float v = V[(size_t)row*DDIM + x0 + tx];
        tw[ty + r*8][tx] = w;
        tv[ty + r*8][tx] = v;
        g_W_bf[(size_t)row*DDIM + x0 + tx] = __float2bfloat16(w);
    }
    __syncthreads();
#pragma unroll
    for (int r = 0; r < 4; r++) {
        int row = x0 + ty + r*8;
        g_Wt_bf[(size_t)row*DDIM + y0 + tx] = __float2bfloat16(tw[tx][ty + r*8]);
        g_Vt_bf[(size_t)row*DDIM + y0 + tx] = __float2bfloat16(tv[tx][ty + r*8]);
    }
}

// ------------------------------ rowprep -----------------------------------
// One WARP per row; 16 values/lane, strided i = lane + 32*j.
// Exact k-th-largest key via 32 register bitplane passes + REDUX; tie
// resolution lowest-index-first via per-j ballots. Also converts this row of
// bottom_up to bf16 (absorbed into the ALU-bound kernel for free).
__global__ __launch_bounds__(256) void rowprep(const float* __restrict__ x,
                                               const float* __restrict__ td,
                                               const float* __restrict__ bu)
{
    __shared__ float sSc[8*DDIM];       // taps, transposed [d][i]
    __shared__ float sphi[8][520];      // per-warp phi row, 3-guard each side

    const int tid = threadIdx.x, wid = tid >> 5, lane = tid & 31;
    const unsigned FULL = 0xffffffffu;

    for (int q = tid; q < 8*DDIM/4; q += 256)
        ((float4*)sSc)[q] = ((const float4*)g_Sct)[q];
    if (lane < 3) sphi[wid][lane] = 0.0f;
    if (lane < 5) sphi[wid][515 + lane] = 0.0f;
    __syncthreads();

    const size_t rb = ((size_t)blockIdx.x * 8 + wid) * DDIM;

    // ---- convert this row of bottom_up to bf16 (coalesced) ----
#pragma unroll
    for (int q = 0; q < 4; q++) {
        int f4 = lane + 32*q;                      // 128 float4 per row
        float4 a = ((const float4*)(bu + rb))[f4];
        __nv_bfloat162 lo = __float22bfloat162_rn(make_float2(a.x, a.y));
        __nv_bfloat162 hi = __float22bfloat162_rn(make_float2(a.z, a.w));
        uint2 o; o.x = *(uint32_t*)&lo; o.y = *(uint32_t*)&hi;
        ((uint2*)(g_bu_bf + rb))[f4] = o;
    }

    float f[16]; uint32_t u[16], d[16];
#pragma unroll
    for (int j = 0; j < 16; j++) {
        f[j] = x[rb + lane + 32*j];
        uint32_t b = __float_as_uint(f[j]);
        u[j] = (b & 0x80000000u) ? ~b : (b | 0x80000000u);   // order-preserving
        d[j] = u[j];
    }

    // ---- bitplane select of the KWTA-th largest key ----
    uint32_t pfx = 0; int rem = KWTA;
#pragma unroll 1
    for (int bit = 31; bit >= 0; --bit) {
        int cl = 0;
#pragma unroll
        for (int j = 0; j < 16; j++) cl += ((d[j] >> bit) == 1u);
        int tot = __reduce_add_sync(FULL, cl);
        if (tot >= rem) {
            uint32_t bm = 1u << bit;
            pfx |= bm;
#pragma unroll
            for (int j = 0; j < 16; j++) d[j] ^= bm;
        } else {
            rem -= tot;
        }
    }

    int cgt = 0;
#pragma unroll
    for (int j = 0; j < 16; j++) cgt += (u[j] > pfx);
    const int need = KWTA - __reduce_add_sync(FULL, cgt);

    // ---- mask + phi/phi' (ties ranked by global index ascending) ----
    const float inv_sqrt2   = 0.7071067811865476f;
    const float inv_sqrt2pi = 0.3989422804014327f;
    int eq_before = 0;
#pragma unroll
    for (int j = 0; j < 16; j++) {
        bool eqj = (u[j] == pfx);
        unsigned bal = __ballot_sync(FULL, eqj);
        bool m = (u[j] > pfx) ||
                 (eqj && (eq_before + __popc(bal & ((1u << lane) - 1u))) < need);
        eq_before += __popc(bal);

        float v = f[j];
        float cdf = 0.5f * (1.0f + erff(v * inv_sqrt2));
        float pdf = expf(-0.5f * v * v) * inv_sqrt2pi;
        float ph = m ? v * cdf : 0.0f;
        float pd = m ? (cdf + v * pdf) : 0.0f;
        int i = lane + 32*j;
        sphi[wid][3 + i] = ph;
        g_phi_bf [rb + i] = __float2bfloat16(ph);
        g_phid_bf[rb + i] = __float2bfloat16(pd);
    }
    __syncwarp();

    // ---- lateral stencil + base ----
#pragma unroll
    for (int j = 0; j < 16; j++) {
        int i = lane + 32*j;
        float lat = 0.0f;
#pragma unroll
        for (int d2 = 0; d2 < 7; d2++)
            lat = fmaf(sphi[wid][i + d2], sSc[d2*DDIM + i], lat);   // [3+i-3+d2]
        float v = f[j];
        float sgn = (v > 0.0f) ? 1.0f : ((v < 0.0f) ? -1.0f : 0.0f);
        float bse = 0.3f*lat + 3.0f*td[rb + i] - 4.0f*v - 1e-6f*sgn;
        g_base_bf[rb + i] = __float2bfloat16(bse);
    }
}

// ------------------------------ HMMA GEMM ---------------------------------
// BM=128, BN=128, BK=32; 256 threads = 8 warps (4m x 2n), warp tile 32x64.
// SMEM rows padded to 80B. 4-stage cp.async, 1 barrier/iter, 2 blocks/SM.
#define BM 128
#define BN 128
#define BK 32
#define NKIT (DDIM / BK)     // 16
#define ASTRIDE 80
#define B_OFF   (BM * ASTRIDE)             // 10240
#define BUFBYTES ((BM + BN) * ASTRIDE)     // 20480
#define GSTAGES 4
#define GSMEM (GSTAGES * BUFBYTES)         // 81920

// mainloop shared by all modes: accumulates C = A[M,K] @ Bt[N,K]^T tile.
__device__ __forceinline__ void gemm_mainloop(
    const __nv_bfloat16* __restrict__ A, const __nv_bfloat16* __restrict__ Bt,
    int m0, int n0, uint32_t sbase, int tid, int wid, int lane,
    int wm, int wn, float acc[2][8][4])
{
    auto load_stage = [&](int k0, int buf) {
#pragma unroll
        for (int i = 0; i < 2; i++) {
            int ch = tid * 2 + i;            // 0..511
            int r = ch >> 2, c = ch & 3;
            cpa16(sbase + buf*BUFBYTES + r*ASTRIDE + c*16,
                  (const char*)A + ((size_t)(m0 + r) * DDIM + k0*BK + c*8) * 2);
            cpa16(sbase + buf*BUFBYTES + B_OFF + r*ASTRIDE + c*16,
                  (const char*)Bt + ((size_t)(n0 + r) * DDIM + k0*BK + c*8) * 2);
        }
    };

    load_stage(0, 0); CP_COMMIT();
    load_stage(1, 1); CP_COMMIT();
    load_stage(2, 2); CP_COMMIT();

#pragma unroll 1
    for (int k0 = 0; k0 < NKIT; k0++) {
        const int buf = k0 & (GSTAGES - 1);
        CP_WAIT2();                 // <=2 of {k0,k0+1,k0+2} pending -> k0 done
        __syncthreads();            // also: everyone done reading buf (k0+3)%4

        if (k0 + 3 < NKIT) load_stage(k0 + 3, (k0 + 3) & (GSTAGES - 1));
        CP_COMMIT();                // always commit: uniform accounting

        const uint32_t abase = sbase + buf*BUFBYTES;
        const uint32_t bbase = abase + B_OFF;
        const int lrow = lane & 15;
#pragma unroll
        for (int ks = 0; ks < 2; ks++) {
            const int lchunk = ks*2 + (lane >> 4);
            uint32_t a[2][4], bf[4][4];
#pragma unroll
            for (int ma = 0; ma < 2; ma++) {
                uint32_t ad = abase + (wm*32 + ma*16 + lrow)*ASTRIDE + lchunk*16;
                LDMX4(a[ma][0], a[ma][1], a[ma][2], a[ma][3], ad);
            }
#pragma unroll
            for (int p = 0; p < 4; p++) {
                uint32_t bd = bbase + (wn*64 + p*16 + lrow)*ASTRIDE + lchunk*16;
                LDMX4(bf[p][0], bf[p][1], bf[p][2], bf[p][3], bd);
            }
#pragma unroll
            for (int ma = 0; ma < 2; ma++)
#pragma unroll
                for (int nn = 0; nn < 8; nn++) {
                    int p = nn >> 1, hi = nn & 1;
                    MMA_BF16(acc[ma][nn], a[ma][0], a[ma][1], a[ma][2], a[ma][3],
                             bf[p][hi], bf[p][2 + hi]);
                }
        }
    }
}

// merged gemm0/gemm1: blockIdx.z==0 -> rd (mode1), ==1 -> err (mode0)
__global__ __launch_bounds__(256, 2)
void gemm01(const float* __restrict__ b_in, const float* __restrict__ b_out)
{
    extern __shared__ char smem[];
    const uint32_t sbase = smem_to_u32(smem);
    const int tid = threadIdx.x, wid = tid >> 5, lane = tid & 31;
    const int wm = wid & 3, wn = wid >> 2;
    const int m0 = blockIdx.y * BM, n0 = blockIdx.x * BN;
    const int mode = blockIdx.z;     // 0: rd, 1: err

    const __nv_bfloat16* A  = mode ? g_phi_bf : g_bu_bf;
    const __nv_bfloat16* Bt = mode ? g_Wt_bf  : g_Vt_bf;
    const float* bias       = mode ? b_out    : b_in;

    float acc[2][8][4];
#pragma unroll
    for (int i = 0; i < 2; i++)
#pragma unroll
        for (int j = 0; j < 8; j++)
#pragma unroll
            for (int q = 0; q < 4; q++) acc[i][j][q] = 0.0f;

    gemm_mainloop(A, Bt, m0, n0, sbase, tid, wid, lane, wm, wn, acc);

    const int group = lane >> 2, qd = lane & 3;
#pragma unroll
    for (int ma = 0; ma < 2; ma++) {
#pragma unroll
        for (int nn = 0; nn < 8; nn++) {
            int col  = n0 + wn*64 + nn*8 + qd*2;
            int row0 = m0 + wm*32 + ma*16 + group;
#pragma unroll
            for (int h = 0; h < 2; h++) {
                int r = row0 + h*8;
                size_t idx = (size_t)r * DDIM + col;
                float v0 = acc[ma][nn][h*2], v1 = acc[ma][nn][h*2 + 1];
                float2 bs = *(const float2*)&bias[col];
                if (mode) {          // err = bu - (phi@W + b_out)
                    uint32_t bb = *(const uint32_t*)&g_bu_bf[idx];
                    float2 bu = __bfloat1622float2(*(__nv_bfloat162*)&bb);
                    __nv_bfloat162 e = __float22bfloat162_rn(
                        make_float2(bu.x - (v0 + bs.x), bu.y - (v1 + bs.y)));
                    *(uint32_t*)&g_err_bf[idx] = *(uint32_t*)&e;
                } else {             // rd = bu@V + b_in + base
                    uint32_t bb = *(const uint32_t*)&g_base_bf[idx];
                    float2 ba = __bfloat1622float2(*(__nv_bfloat162*)&bb);
                    __nv_bfloat162 o = __float22bfloat162_rn(
                        make_float2(v0 + bs.x + ba.x, v1 + bs.y + ba.y));
                    *(uint32_t*)&g_rd_bf[idx] = *(uint32_t*)&o;
                }
            }
        }
    }
}

__global__ __launch_bounds__(256, 2)
void gemm2()
{
    extern __shared__ char smem[];
    const uint32_t sbase = smem_to_u32(smem);
    const int tid = threadIdx.x, wid = tid >> 5, lane = tid & 31;
    const int wm = wid & 3, wn = wid >> 2;
    const int m0 = blockIdx.y * BM, n0 = blockIdx.x * BN;

    float acc[2][8][4];
#pragma unroll
    for (int i = 0; i < 2; i++)
#pragma unroll
        for (int j = 0; j < 8; j++)
#pragma unroll
            for (int q = 0; q < 4; q++) acc[i][j][q] = 0.0f;

    gemm_mainloop(g_err_bf, g_W_bf, m0, n0, sbase, tid, wid, lane, wm, wn, acc);

    const int group = lane >> 2, qd = lane & 3;
    float lsum = 0.0f;
#pragma unroll
    for (int ma = 0; ma < 2; ma++) {
#pragma unroll
        for (int nn = 0; nn < 8; nn++) {
            int col  = n0 + wn*64 + nn*8 + qd*2;
            int row0 = m0 + wm*32 + ma*16 + group;
#pragma unroll
            for (int h = 0; h < 2; h++) {
                int r = row0 + h*8;
                size_t idx = (size_t)r * DDIM + col;
                float v0 = acc[ma][nn][h*2], v1 = acc[ma][nn][h*2 + 1];
                uint32_t pu = *(const uint32_t*)&g_phid_bf[idx];
                uint32_t ru = *(const uint32_t*)&g_rd_bf[idx];
                float2 ph = __bfloat1622float2(*(__nv_bfloat162*)&pu);
                float2 rd = __bfloat1622float2(*(__nv_bfloat162*)&ru);
                float s0 = fmaf(v0, ph.x, rd.x);
                float s1 = fmaf(v1, ph.y, rd.y);
                __nv_bfloat162 o = __float22bfloat162_rn(make_float2(s0, s1));
                *(uint32_t*)&g_sg_bf[idx] = *(uint32_t*)&o;
                lsum = fmaf(s0, s0, fmaf(s1, s1, lsum));
            }
        }
    }

    __shared__ float red[8];
#pragma unroll
    for (int o = 16; o > 0; o >>= 1) lsum += __shfl_xor_sync(0xffffffff, lsum, o);
    if (lane == 0) red[wid] = lsum;
    __syncthreads();
    if (tid == 0) {
        float s = 0.0f;
#pragma unroll
        for (int w = 0; w < 8; w++) s += red[w];
        atomicAdd(&g_norm2, (double)s);
    }
}

// ------------------------------ finalize ----------------------------------
// 8 elements per thread: out = clip(x + scale*sg, -5, 5)
__global__ __launch_bounds__(256) void finalize(const float* __restrict__ x,
                                                const int* __restrict__ step,
                                                float* __restrict__ out)
{
    float c = 0.5f * (0.8f / (1.0f + 0.1f * (float)(*step)));
    float n = c * (float)sqrt(g_norm2);
    float scale = (n > 1.0f) ? (c / (n + 1e-8f)) : c;

    size_t i8 = (size_t)(blockIdx.x * blockDim.x + threadIdx.x) * 8;
    uint4 su = *(const uint4*)&g_sg_bf[i8];
    const uint32_t* sp = (const uint32_t*)&su;
#pragma unroll
    for (int h = 0; h < 2; h++) {
        float4 xv = *(const float4*)(x + i8 + h*4);
        float2 sa = __bfloat1622float2(*(__nv_bfloat162*)&sp[h*2]);
        float2 sb = __bfloat1622float2(*(__nv_bfloat162*)&sp[h*2 + 1]);
        float4 o;
        o.x = fminf(5.0f, fmaxf(-5.0f, fmaf(scale, sa.x, xv.x)));
        o.y = fminf(5.0f, fmaxf(-5.0f, fmaf(scale, sa.y, xv.y)));
        o.z = fminf(5.0f, fmaxf(-5.0f, fmaf(scale, sb.x, xv.z)));
        o.w = fminf(5.0f, fmaxf(-5.0f, fmaf(scale, sb.y, xv.w)));
        *(float4*)(out + i8 + h*4) = o;
    }
}

// ---------------------------------------------------------------------------
extern "C" void kernel_launch(void* const* d_in, const int* in_sizes, int n_in,
                              void* d_out, int out_size)
{
    const float* bottom_up = (const float*)d_in[0];
    const float* td        = (const float*)d_in[1];
    const float* x         = (const float*)d_in[2];
    const float* V         = (const float*)d_in[3];
    const float* b_in      = (const float*)d_in[4];
    const float* W         = (const float*)d_in[5];
    const float* b_out     = (const float*)d_in[6];
    const float* L         = (const float*)d_in[7];
    const float* Lm        = (const float*)d_in[8];
    const int*   step      = (const int*)  d_in[9];
    float* out = (float*)d_out;

    cudaFuncSetAttribute(gemm01, cudaFuncAttributeMaxDynamicSharedMemorySize, GSMEM);
    cudaFuncSetAttribute(gemm2,  cudaFuncAttributeMaxDynamicSharedMemorySize, GSMEM);

    build_sc<<<2, 256>>>(L, Lm);
    transpose_prep<<<dim3(16, 16), dim3(32, 8)>>>(W, V);
    rowprep<<<BDIM / 8, 256>>>(x, td, bottom_up);

    // z=0: rd = bu@V + b_in + base ; z=1: err = bu - (phi@W + b_out)
    gemm01<<<dim3(DDIM / BN, BDIM / BM, 2), 256, GSMEM>>>(b_in, b_out);
    // sg = (err@W^T)*phi' + rd ; ||sg||^2
    gemm2<<<dim3(DDIM / BN, BDIM / BM), 256, GSMEM>>>();

    finalize<<<NTOT / 8 / 256, 256>>>(x, step, out);
}

// round 11
// speedup vs baseline: 2.1735x; 1.1738x over previous
#include <cuda_runtime.h>
#include <cuda_bf16.h>
#include <math.h>
#include <stdint.h>

// ---------------------------------------------------------------------------
// PredictiveColumn on GB300 via mma.sync bf16.
//   build_sc       : transposed 7-tap band g_Sct[d][n] + zero norm
//   transpose_prep : bf16 W / W^T / V^T via tiled smem transpose
//   rowprep        : WARP-PER-ROW kWTA on top-16-bit keys (16 bitplanes+REDUX),
//                    phi(bf16), phi'(bf16), base(bf16), bu fp32->bf16
//   gemm01 (z=0)   : rd  = bu @ V + b_in + base  -> bf16    (B = V^T)
//   gemm01 (z=1)   : err = bu - (phi @ W + b_out) -> bf16   (B = W^T)
//   gemm2          : sg  = (err @ W^T)*phi' + rd -> bf16 ; ||sg||^2  (B = W)
//   finalize       : out = clip(x + scale*sg, -5, 5)
// GEMM: 128x128 tile, BK=64, 256 thr, 3-stage cp.async, 8 iters, 2 blocks/SM.
// ---------------------------------------------------------------------------

#define BDIM 16384
#define DDIM 512
#define KWTA 128
#define NTOT (BDIM*DDIM)

__device__ __nv_bfloat16 g_bu_bf  [NTOT];
__device__ __nv_bfloat16 g_phi_bf [NTOT];
__device__ __nv_bfloat16 g_err_bf [NTOT];
__device__ __nv_bfloat16 g_phid_bf[NTOT];
__device__ __nv_bfloat16 g_base_bf[NTOT];
__device__ __nv_bfloat16 g_rd_bf  [NTOT];
__device__ __nv_bfloat16 g_sg_bf  [NTOT];
__device__ __nv_bfloat16 g_W_bf [DDIM*DDIM];
__device__ __nv_bfloat16 g_Wt_bf[DDIM*DDIM];
__device__ __nv_bfloat16 g_Vt_bf[DDIM*DDIM];
__device__ float  g_Sct[8*DDIM];     // [d][n], d=7 row is zero
__device__ double g_norm2;

// ------------------------------ helpers -----------------------------------
__device__ __forceinline__ uint32_t smem_to_u32(const void* p) {
    uint32_t a;
    asm("{ .reg .u64 t; cvta.to.shared.u64 t, %1; cvt.u32.u64 %0, t; }" : "=r"(a) : "l"(p));
    return a;
}
__device__ __forceinline__ void cpa16(uint32_t dst, const void* src) {
    asm volatile("cp.async.cg.shared.global [%0], [%1], 16;" :: "r"(dst), "l"(src));
}
#define CP_COMMIT() asm volatile("cp.async.commit_group;" ::: "memory")
#define CP_WAIT1()  asm volatile("cp.async.wait_group 1;" ::: "memory")

#define LDMX4(r0, r1, r2, r3, addr) \
    asm volatile("ldmatrix.sync.aligned.m8n8.x4.shared.b16 {%0,%1,%2,%3}, [%4];" \
                 : "=r"(r0), "=r"(r1), "=r"(r2), "=r"(r3) : "r"(addr))

#define MMA_BF16(c, a0, a1, a2, a3, b0, b1) \
    asm volatile("mma.sync.aligned.m16n8k16.row.col.f32.bf16.bf16.f32 " \
                 "{%0,%1,%2,%3}, {%4,%5,%6,%7}, {%8,%9}, {%0,%1,%2,%3};" \
                 : "+f"((c)[0]), "+f"((c)[1]), "+f"((c)[2]), "+f"((c)[3]) \
                 : "r"(a0), "r"(a1), "r"(a2), "r"(a3), "r"(b0), "r"(b1))

// ------------------------------ prep kernels ------------------------------
__global__ __launch_bounds__(256) void build_sc(const float* __restrict__ L,
                                                const float* __restrict__ Lm)
{
    int n = blockIdx.x * 256 + threadIdx.x;
    if (n == 0) g_norm2 = 0.0;
    if (n >= DDIM) return;
#pragma unroll
    for (int d = 0; d < 7; d++) {
        int j = n - 3 + d;
        float v = 0.0f;
        if (j >= 0 && j < DDIM) v = L[(size_t)j*DDIM + n] * Lm[(size_t)j*DDIM + n];
        g_Sct[d*DDIM + n] = v;
    }
    g_Sct[7*DDIM + n] = 0.0f;
}

// tiled transpose: W -> W_bf, Wt_bf ; V -> Vt_bf. 32x32 tiles, block (32,8).
__global__ __launch_bounds__(256) void transpose_prep(const float* __restrict__ W,
                                                      const float* __restrict__ V)
{
    __shared__ float tw[32][33];
    __shared__ float tv[32][33];
    const int tx = threadIdx.x, ty = threadIdx.y;
    const int x0 = blockIdx.x * 32, y0 = blockIdx.y * 32;
#pragma unroll
    for (int r = 0; r < 4; r++) {
        int row = y0 + ty + r*8;
        float w = W[(size_t)row*DDIM + x0 + tx];
        float v = V[(size_t)row*DDIM + x0 + tx];
        tw[ty + r*8][tx] = w;
        tv[ty + r*8][tx] = v;
        g_W_bf[(size_t)row*DDIM + x0 + tx] = __float2bfloat16(w);
    }
    __syncthreads();
#pragma unroll
    for (int r = 0; r < 4; r++) {
        int row = x0 + ty + r*8;
        g_Wt_bf[(size_t)row*DDIM + y0 + tx] = __float2bfloat16(tw[tx][ty + r*8]);
        g_Vt_bf[(size_t)row*DDIM + y0 + tx] = __float2bfloat16(tv[tx][ty + r*8]);
    }
}

// ------------------------------ rowprep -----------------------------------
// One WARP per row; 16 values/lane, strided i = lane + 32*j.
// k-th-largest selected on the TOP 16 BITS of the order-preserving key
// (16 bitplane passes + REDUX); ties within a 16-bit prefix class ranked by
// global index ascending. Also converts this row of bottom_up to bf16.
__global__ __launch_bounds__(256) void rowprep(const float* __restrict__ x,
                                               const float* __restrict__ td,
                                               const float* __restrict__ bu)
{
    __shared__ float sSc[8*DDIM];       // taps, transposed [d][i]
    __shared__ float sphi[8][520];      // per-warp phi row, 3-guard each side

    const int tid = threadIdx.x, wid = tid >> 5, lane = tid & 31;
    const unsigned FULL = 0xffffffffu;

    for (int q = tid; q < 8*DDIM/4; q += 256)
        ((float4*)sSc)[q] = ((const float4*)g_Sct)[q];
    if (lane < 3) sphi[wid][lane] = 0.0f;
    if (lane < 5) sphi[wid][515 + lane] = 0.0f;
    __syncthreads();

    const size_t rb = ((size_t)blockIdx.x * 8 + wid) * DDIM;

    // ---- convert this row of bottom_up to bf16 (coalesced) ----
#pragma unroll
    for (int q = 0; q < 4; q++) {
        int f4 = lane + 32*q;                      // 128 float4 per row
        float4 a = ((const float4*)(bu + rb))[f4];
        __nv_bfloat162 lo = __float22bfloat162_rn(make_float2(a.x, a.y));
        __nv_bfloat162 hi = __float22bfloat162_rn(make_float2(a.z, a.w));
        uint2 o; o.x = *(uint32_t*)&lo; o.y = *(uint32_t*)&hi;
        ((uint2*)(g_bu_bf + rb))[f4] = o;
    }

    float f[16]; uint32_t u[16], d[16];
#pragma unroll
    for (int j = 0; j < 16; j++) {
        f[j] = x[rb + lane + 32*j];
        uint32_t b = __float_as_uint(f[j]);
        b = (b & 0x80000000u) ? ~b : (b | 0x80000000u);   // order-preserving
        u[j] = b >> 16;                                   // 16-bit key
        d[j] = u[j];
    }

    // ---- bitplane select of the KWTA-th largest 16-bit key ----
    uint32_t pfx = 0; int rem = KWTA;
#pragma unroll 1
    for (int bit = 15; bit >= 0; --bit) {
        int cl = 0;
#pragma unroll
        for (int j = 0; j < 16; j++) cl += ((d[j] >> bit) == 1u);
        int tot = __reduce_add_sync(FULL, cl);
        if (tot >= rem) {
            uint32_t bm = 1u << bit;
            pfx |= bm;
#pragma unroll
            for (int j = 0; j < 16; j++) d[j] ^= bm;
        } else {
            rem -= tot;
        }
    }

    int cgt = 0;
#pragma unroll
    for (int j = 0; j < 16; j++) cgt += (u[j] > pfx);
    const int need = KWTA - __reduce_add_sync(FULL, cgt);

    // ---- mask + phi/phi' (ties ranked by global index ascending) ----
    const float inv_sqrt2   = 0.7071067811865476f;
    const float inv_sqrt2pi = 0.3989422804014327f;
    int eq_before = 0;
#pragma unroll
    for (int j = 0; j < 16; j++) {
        bool eqj = (u[j] == pfx);
        unsigned bal = __ballot_sync(FULL, eqj);
        bool m = (u[j] > pfx) ||
                 (eqj && (eq_before + __popc(bal & ((1u << lane) - 1u))) < need);
        eq_before += __popc(bal);

        float v = f[j];
        float cdf = 0.5f * (1.0f + erff(v * inv_sqrt2));
        float pdf = expf(-0.5f * v * v) * inv_sqrt2pi;
        float ph = m ? v * cdf : 0.0f;
        float pd = m ? (cdf + v * pdf) : 0.0f;
        int i = lane + 32*j;
        sphi[wid][3 + i] = ph;
        g_phi_bf [rb + i] = __float2bfloat16(ph);
        g_phid_bf[rb + i] = __float2bfloat16(pd);
    }
    __syncwarp();

    // ---- lateral stencil + base ----
#pragma unroll
    for (int j = 0; j < 16; j++) {
        int i = lane + 32*j;
        float lat = 0.0f;
#pragma unroll
        for (int d2 = 0; d2 < 7; d2++)
            lat = fmaf(sphi[wid][i + d2], sSc[d2*DDIM + i], lat);   // [3+i-3+d2]
        float v = f[j];
        float sgn = (v > 0.0f) ? 1.0f : ((v < 0.0f) ? -1.0f : 0.0f);
        float bse = 0.3f*lat + 3.0f*td[rb + i] - 4.0f*v - 1e-6f*sgn;
        g_base_bf[rb + i] = __float2bfloat16(bse);
    }
}

// ------------------------------ HMMA GEMM ---------------------------------
// BM=128, BN=128, BK=64; 256 threads = 8 warps (4m x 2n), warp tile 32x64.
// SMEM rows 128B data + 16B pad = 144B. 3-stage cp.async, 8 iters,
// 1 barrier/iter, 2 blocks/SM.
#define BM 128
#define BN 128
#define BK 64
#define NKIT (DDIM / BK)     // 8
#define ASTRIDE 144
#define B_OFF   (BM * ASTRIDE)             // 18432
#define BUFBYTES ((BM + BN) * ASTRIDE)     // 36864
#define GSTAGES 3
#define GSMEM (GSTAGES * BUFBYTES)         // 110592

// mainloop shared by all modes: accumulates C = A[M,K] @ Bt[N,K]^T tile.
__device__ __forceinline__ void gemm_mainloop(
    const __nv_bfloat16* __restrict__ A, const __nv_bfloat16* __restrict__ Bt,
    int m0, int n0, uint32_t sbase, int tid, int lane,
    int wm, int wn, float acc[2][8][4])
{
    // stage = A:128 rows x 8 chunks + B:128 rows x 8 chunks = 2048 cpa16,
    // 8 per thread, coalesced (consecutive tid -> consecutive 16B of a row).
    auto load_stage = [&](int k0, int buf) {
        const uint32_t dA = sbase + buf*BUFBYTES;
        const uint32_t dB = dA + B_OFF;
#pragma unroll
        for (int i = 0; i < 4; i++) {
            int ch = i*256 + tid;            // 0..1023
            int r = ch >> 3, c = ch & 7;
            cpa16(dA + r*ASTRIDE + c*16,
                  (const char*)A + ((size_t)(m0 + r) * DDIM + k0*BK + c*8) * 2);
            cpa16(dB + r*ASTRIDE + c*16,
                  (const char*)Bt + ((size_t)(n0 + r) * DDIM + k0*BK + c*8) * 2);
        }
    };

    load_stage(0, 0); CP_COMMIT();
    load_stage(1, 1); CP_COMMIT();

#pragma unroll 1
    for (int k0 = 0; k0 < NKIT; k0++) {
        const int buf = k0 % GSTAGES;
        CP_WAIT1();                 // <=1 pending -> stage k0 complete
        __syncthreads();            // buf (k0+2)%3 readers are done (iter k0-1)

        if (k0 + 2 < NKIT) load_stage(k0 + 2, (k0 + 2) % GSTAGES);
        CP_COMMIT();                // always commit: uniform accounting

        const uint32_t abase = sbase + buf*BUFBYTES;
        const uint32_t bbase = abase + B_OFF;
        const int lrow = lane & 15;
#pragma unroll
        for (int ks = 0; ks < 4; ks++) {
            const int lchunk = ks*2 + (lane >> 4);
            uint32_t a[2][4], bf[4][4];
#pragma unroll
            for (int ma = 0; ma < 2; ma++) {
                uint32_t ad = abase + (wm*32 + ma*16 + lrow)*ASTRIDE + lchunk*16;
                LDMX4(a[ma][0], a[ma][1], a[ma][2], a[ma][3], ad);
            }
#pragma unroll
            for (int p = 0; p < 4; p++) {
                uint32_t bd = bbase + (wn*64 + p*16 + lrow)*ASTRIDE + lchunk*16;
                LDMX4(bf[p][0], bf[p][1], bf[p][2], bf[p][3], bd);
            }
#pragma unroll
            for (int ma = 0; ma < 2; ma++)
#pragma unroll
                for (int nn = 0; nn < 8; nn++) {
                    int p = nn >> 1, hi = nn & 1;
                    MMA_BF16(acc[ma][nn], a[ma][0], a[ma][1], a[ma][2], a[ma][3],
                             bf[p][hi], bf[p][2 + hi]);
                }
        }
    }
}

// merged gemm0/gemm1: blockIdx.z==0 -> rd (mode1), ==1 -> err (mode0)
__global__ __launch_bounds__(256, 2)
void gemm01(const float* __restrict__ b_in, const float* __restrict__ b_out)
{
    extern __shared__ char smem[];
    const uint32_t sbase = smem_to_u32(smem);
    const int tid = threadIdx.x, wid = tid >> 5, lane = tid & 31;
    const int wm = wid & 3, wn = wid >> 2;
    const int m0 = blockIdx.y * BM, n0 = blockIdx.x * BN;
    const int mode = blockIdx.z;     // 0: rd, 1: err

    const __nv_bfloat16* A  = mode ? g_phi_bf : g_bu_bf;
    const __nv_bfloat16* Bt = mode ? g_Wt_bf  : g_Vt_bf;
    const float* bias       = mode ? b_out    : b_in;

    float acc[2][8][4];
#pragma unroll
    for (int i = 0; i < 2; i++)
#pragma unroll
        for (int j = 0; j < 8; j++)
#pragma unroll
            for (int q = 0; q < 4; q++) acc[i][j][q] = 0.0f;

    gemm_mainloop(A, Bt, m0, n0, sbase, tid, lane, wm, wn, acc);

    const int group = lane >> 2, qd = lane & 3;
#pragma unroll
    for (int ma = 0; ma < 2; ma++) {
#pragma unroll
        for (int nn = 0; nn < 8; nn++) {
            int col  = n0 + wn*64 + nn*8 + qd*2;
            int row0 = m0 + wm*32 + ma*16 + group;
#pragma unroll
            for (int h = 0; h < 2; h++) {
                int r = row0 + h*8;
                size_t idx = (size_t)r * DDIM + col;
                float v0 = acc[ma][nn][h*2], v1 = acc[ma][nn][h*2 + 1];
                float2 bs = *(const float2*)&bias[col];
                if (mode) {          // err = bu - (phi@W + b_out)
                    uint32_t bb = *(const uint32_t*)&g_bu_bf[idx];
                    float2 bu = __bfloat1622float2(*(__nv_bfloat162*)&bb);
                    __nv_bfloat162 e = __float22bfloat162_rn(
                        make_float2(bu.x - (v0 + bs.x), bu.y - (v1 + bs.y)));
                    *(uint32_t*)&g_err_bf[idx] = *(uint32_t*)&e;
                } else {             // rd = bu@V + b_in + base
                    uint32_t bb = *(const uint32_t*)&g_base_bf[idx];
                    float2 ba = __bfloat1622float2(*(__nv_bfloat162*)&bb);
                    __nv_bfloat162 o = __float22bfloat162_rn(
                        make_float2(v0 + bs.x + ba.x, v1 + bs.y + ba.y));
                    *(uint32_t*)&g_rd_bf[idx] = *(uint32_t*)&o;
                }
            }
        }
    }
}

__global__ __launch_bounds__(256, 2)
void gemm2()
{
    extern __shared__ char smem[];
    const uint32_t sbase = smem_to_u32(smem);
    const int tid = threadIdx.x, wid = tid >> 5, lane = tid & 31;
    const int wm = wid & 3, wn = wid >> 2;
    const int m0 = blockIdx.y * BM, n0 = blockIdx.x * BN;

    float acc[2][8][4];
#pragma unroll
    for (int i = 0; i < 2; i++)
#pragma unroll
        for (int j = 0; j < 8; j++)
#pragma unroll
            for (int q = 0; q < 4; q++) acc[i][j][q] = 0.0f;

    gemm_mainloop(g_err_bf, g_W_bf, m0, n0, sbase, tid, lane, wm, wn, acc);

    const int group = lane >> 2, qd = lane & 3;
    float lsum = 0.0f;
#pragma unroll
    for (int ma = 0; ma < 2; ma++) {
#pragma unroll
        for (int nn = 0; nn < 8; nn++) {
            int col  = n0 + wn*64 + nn*8 + qd*2;
            int row0 = m0 + wm*32 + ma*16 + group;
#pragma unroll
            for (int h = 0; h < 2; h++) {
                int r = row0 + h*8;
                size_t idx = (size_t)r * DDIM + col;
                float v0 = acc[ma][nn][h*2], v1 = acc[ma][nn][h*2 + 1];
                uint32_t pu = *(const uint32_t*)&g_phid_bf[idx];
                uint32_t ru = *(const uint32_t*)&g_rd_bf[idx];
                float2 ph = __bfloat1622float2(*(__nv_bfloat162*)&pu);
                float2 rd = __bfloat1622float2(*(__nv_bfloat162*)&ru);
                float s0 = fmaf(v0, ph.x, rd.x);
                float s1 = fmaf(v1, ph.y, rd.y);
                __nv_bfloat162 o = __float22bfloat162_rn(make_float2(s0, s1));
                *(uint32_t*)&g_sg_bf[idx] = *(uint32_t*)&o;
                lsum = fmaf(s0, s0, fmaf(s1, s1, lsum));
            }
        }
    }

    __shared__ float red[8];
#pragma unroll
    for (int o = 16; o > 0; o >>= 1) lsum += __shfl_xor_sync(0xffffffff, lsum, o);
    if (lane == 0) red[wid] = lsum;
    __syncthreads();
    if (tid == 0) {
        float s = 0.0f;
#pragma unroll
        for (int w = 0; w < 8; w++) s += red[w];
        atomicAdd(&g_norm2, (double)s);
    }
}

// ------------------------------ finalize ----------------------------------
// 8 elements per thread: out = clip(x + scale*sg, -5, 5)
__global__ __launch_bounds__(256) void finalize(const float* __restrict__ x,
                                                const int* __restrict__ step,
                                                float* __restrict__ out)
{
    float c = 0.5f * (0.8f / (1.0f + 0.1f * (float)(*step)));
    float n = c * (float)sqrt(g_norm2);
    float scale = (n > 1.0f) ? (c / (n + 1e-8f)) : c;

    size_t i8 = (size_t)(blockIdx.x * blockDim.x + threadIdx.x) * 8;
    uint4 su = *(const uint4*)&g_sg_bf[i8];
    const uint32_t* sp = (const uint32_t*)&su;
#pragma unroll
    for (int h = 0; h < 2; h++) {
        float4 xv = *(const float4*)(x + i8 + h*4);
        float2 sa = __bfloat1622float2(*(__nv_bfloat162*)&sp[h*2]);
        float2 sb = __bfloat1622float2(*(__nv_bfloat162*)&sp[h*2 + 1]);
        float4 o;
        o.x = fminf(5.0f, fmaxf(-5.0f, fmaf(scale, sa.x, xv.x)));
        o.y = fminf(5.0f, fmaxf(-5.0f, fmaf(scale, sa.y, xv.y)));
        o.z = fminf(5.0f, fmaxf(-5.0f, fmaf(scale, sb.x, xv.z)));
        o.w = fminf(5.0f, fmaxf(-5.0f, fmaf(scale, sb.y, xv.w)));
        *(float4*)(out + i8 + h*4) = o;
    }
}

// ---------------------------------------------------------------------------
extern "C" void kernel_launch(void* const* d_in, const int* in_sizes, int n_in,
                              void* d_out, int out_size)
{
    const float* bottom_up = (const float*)d_in[0];
    const float* td        = (const float*)d_in[1];
    const float* x         = (const float*)d_in[2];
    const float* V         = (const float*)d_in[3];
    const float* b_in      = (const float*)d_in[4];
    const float* W         = (const float*)d_in[5];
    const float* b_out     = (const float*)d_in[6];
    const float* L         = (const float*)d_in[7];
    const float* Lm        = (const float*)d_in[8];
    const int*   step      = (const int*)  d_in[9];
    float* out = (float*)d_out;

    cudaFuncSetAttribute(gemm01, cudaFuncAttributeMaxDynamicSharedMemorySize, GSMEM);
    cudaFuncSetAttribute(gemm2,  cudaFuncAttributeMaxDynamicSharedMemorySize, GSMEM);

    build_sc<<<2, 256>>>(L, Lm);
    transpose_prep<<<dim3(16, 16), dim3(32, 8)>>>(W, V);
    rowprep<<<BDIM / 8, 256>>>(x, td, bottom_up);

    // z=0: rd = bu@V + b_in + base ; z=1: err = bu - (phi@W + b_out)
    gemm01<<<dim3(DDIM / BN, BDIM / BM, 2), 256, GSMEM>>>(b_in, b_out);
    // sg = (err@W^T)*phi' + rd ; ||sg||^2
    gemm2<<<dim3(DDIM / BN, BDIM / BM), 256, GSMEM>>>();

    finalize<<<NTOT / 8 / 256, 256>>>(x, step, out);
}

// round 13
// speedup vs baseline: 2.1977x; 1.0111x over previous
#include <cuda_runtime.h>
#include <cuda_bf16.h>
#include <math.h>
#include <stdint.h>

// ---------------------------------------------------------------------------
// PredictiveColumn on GB300 via mma.sync FP8 (e4m3).
//   build_sc     : transposed 7-tap band g_Sct[d][n] + zero norm
//   prep_weights : fp8 W / W^T / V^T (x16 scale) via tiled smem transpose
//   rowprep      : WARP-PER-ROW kWTA on top-16-bit keys, phi(fp8 x4),
//                  phi'(bf16), base(bf16), bu -> bf16 + fp8(x4)
//   gemm01 (z=0) : rd  = bu @ V + b_in + base -> bf16     (B = V^T fp8)
//   gemm01 (z=1) : err = bu - (phi @ W + b_out) -> fp8    (B = W^T fp8)
//   gemm2        : sg  = (err @ W^T)*phi' + rd -> bf16 ; ||sg||^2 (B = W fp8)
//   finalize     : out = clip(x + scale*sg, -5, 5)
// GEMM: 128x128 tile, BK=128 (4 iters!), 3-stage cp.async, 2 blocks/SM,
// m16n8k32 e4m3 MMA, operands via ldmatrix.b16 (layout matches fp8 fragment).
// Scales: A x4, B x16, epilogue x(1/64).
// ---------------------------------------------------------------------------

#define BDIM 16384
#define DDIM 512
#define KWTA 128
#define NTOT (BDIM*DDIM)

__device__ uint8_t g_bu_f8 [NTOT];
__device__ uint8_t g_phi_f8[NTOT];
__device__ uint8_t g_err_f8[NTOT];
__device__ __nv_bfloat16 g_bu_bf  [NTOT];
__device__ __nv_bfloat16 g_phid_bf[NTOT];
__device__ __nv_bfloat16 g_base_bf[NTOT];
__device__ __nv_bfloat16 g_rd_bf  [NTOT];
__device__ __nv_bfloat16 g_sg_bf  [NTOT];
__device__ uint8_t g_W_f8 [DDIM*DDIM];
__device__ uint8_t g_Wt_f8[DDIM*DDIM];
__device__ uint8_t g_Vt_f8[DDIM*DDIM];
__device__ float  g_Sct[8*DDIM];     // [d][n], d=7 row is zero
__device__ double g_norm2;

#define SCL_INV 0.015625f            // 1/(4*16)

// ------------------------------ helpers -----------------------------------
__device__ __forceinline__ uint32_t smem_to_u32(const void* p) {
    uint32_t a;
    asm("{ .reg .u64 t; cvta.to.shared.u64 t, %1; cvt.u32.u64 %0, t; }" : "=r"(a) : "l"(p));
    return a;
}
__device__ __forceinline__ void cpa16(uint32_t dst, const void* src) {
    asm volatile("cp.async.cg.shared.global [%0], [%1], 16;" :: "r"(dst), "l"(src));
}
#define CP_COMMIT() asm volatile("cp.async.commit_group;" ::: "memory")
#define CP_WAIT1()  asm volatile("cp.async.wait_group 1;" ::: "memory")

#define LDMX4(r0, r1, r2, r3, addr) \
    asm volatile("ldmatrix.sync.aligned.m8n8.x4.shared.b16 {%0,%1,%2,%3}, [%4];" \
                 : "=r"(r0), "=r"(r1), "=r"(r2), "=r"(r3) : "r"(addr))

#define MMA_FP8(c, a0, a1, a2, a3, b0, b1) \
    asm volatile("mma.sync.aligned.m16n8k32.row.col.f32.e4m3.e4m3.f32 " \
                 "{%0,%1,%2,%3}, {%4,%5,%6,%7}, {%8,%9}, {%0,%1,%2,%3};" \
                 : "+f"((c)[0]), "+f"((c)[1]), "+f"((c)[2]), "+f"((c)[3]) \
                 : "r"(a0), "r"(a1), "r"(a2), "r"(a3), "r"(b0), "r"(b1))

// first source -> upper byte, second -> lower byte (matches bf16x2 cvt)
__device__ __forceinline__ uint32_t pack4_e4m3(float f0, float f1, float f2, float f3) {
    uint16_t lo, hi;
    asm("cvt.rn.satfinite.e4m3x2.f32 %0, %1, %2;" : "=h"(lo) : "f"(f1), "f"(f0));
    asm("cvt.rn.satfinite.e4m3x2.f32 %0, %1, %2;" : "=h"(hi) : "f"(f3), "f"(f2));
    return (uint32_t)lo | ((uint32_t)hi << 16);
}
__device__ __forceinline__ uint16_t pack2_e4m3(float f0, float f1) {
    uint16_t r;
    asm("cvt.rn.satfinite.e4m3x2.f32 %0, %1, %2;" : "=h"(r) : "f"(f1), "f"(f0));
    return r;
}
__device__ __forceinline__ uint8_t cvt1_e4m3(float f) {
    uint16_t r;
    asm("cvt.rn.satfinite.e4m3x2.f32 %0, %1, %2;" : "=h"(r) : "f"(0.0f), "f"(f));
    return (uint8_t)r;
}

// ------------------------------ prep kernels ------------------------------
__global__ __launch_bounds__(256) void build_sc(const float* __restrict__ L,
                                                const float* __restrict__ Lm)
{
    int n = blockIdx.x * 256 + threadIdx.x;
    if (n == 0) g_norm2 = 0.0;
    if (n >= DDIM) return;
#pragma unroll
    for (int d = 0; d < 7; d++) {
        int j = n - 3 + d;
        float v = 0.0f;
        if (j >= 0 && j < DDIM) v = L[(size_t)j*DDIM + n] * Lm[(size_t)j*DDIM + n];
        g_Sct[d*DDIM + n] = v;
    }
    g_Sct[7*DDIM + n] = 0.0f;
}

// tiled transpose: W -> W_f8, Wt_f8 ; V -> Vt_f8 (all x16). 32x32 tiles.
__global__ __launch_bounds__(256) void prep_weights(const float* __restrict__ W,
                                                    const float* __restrict__ V)
{
    __shared__ float tw[32][33];
    __shared__ float tv[32][33];
    const int tx = threadIdx.x, ty = threadIdx.y;
    const int x0 = blockIdx.x * 32, y0 = blockIdx.y * 32;
#pragma unroll
    for (int r = 0; r < 4; r++) {
        int row = y0 + ty + r*8;
        float w = W[(size_t)row*DDIM + x0 + tx];
        float v = V[(size_t)row*DDIM + x0 + tx];
        tw[ty + r*8][tx] = w;
        tv[ty + r*8][tx] = v;
        g_W_f8[(size_t)row*DDIM + x0 + tx] = cvt1_e4m3(w * 16.0f);
    }
    __syncthreads();
#pragma unroll
    for (int r = 0; r < 4; r++) {
        int row = x0 + ty + r*8;
        g_Wt_f8[(size_t)row*DDIM + y0 + tx] = cvt1_e4m3(tw[tx][ty + r*8] * 16.0f);
        g_Vt_f8[(size_t)row*DDIM + y0 + tx] = cvt1_e4m3(tv[tx][ty + r*8] * 16.0f);
    }
}

// ------------------------------ rowprep -----------------------------------
// One WARP per row; 16 values/lane, strided i = lane + 32*j.
// kWTA on top-16-bit keys (16 bitplane passes + REDUX); ties by index.
// Emits: phi fp8(x4), phi' bf16, base bf16, bu bf16 + fp8(x4).
__global__ __launch_bounds__(256) void rowprep(const float* __restrict__ x,
                                               const float* __restrict__ td,
                                               const float* __restrict__ bu)
{
    __shared__ float sSc[8*DDIM];       // taps, transposed [d][i]
    __shared__ float sphi[8][524];      // per-warp phi row, 4-guard front, 8 back

    const int tid = threadIdx.x, wid = tid >> 5, lane = tid & 31;
    const unsigned FULL = 0xffffffffu;

    for (int q = tid; q < 8*DDIM/4; q += 256)
        ((float4*)sSc)[q] = ((const float4*)g_Sct)[q];
    if (lane < 4) sphi[wid][lane] = 0.0f;
    if (lane < 8) sphi[wid][516 + lane] = 0.0f;
    __syncthreads();

    const size_t rb = ((size_t)blockIdx.x * 8 + wid) * DDIM;

    // ---- convert this row of bottom_up to bf16 + fp8(x4) ----
#pragma unroll
    for (int q = 0; q < 4; q++) {
        int f4 = lane + 32*q;                      // 128 float4 per row
        float4 a = ((const float4*)(bu + rb))[f4];
        __nv_bfloat162 lo = __float22bfloat162_rn(make_float2(a.x, a.y));
        __nv_bfloat162 hi = __float22bfloat162_rn(make_float2(a.z, a.w));
        uint2 o; o.x = *(uint32_t*)&lo; o.y = *(uint32_t*)&hi;
        ((uint2*)(g_bu_bf + rb))[f4] = o;
        ((uint32_t*)(g_bu_f8 + rb))[f4] =
            pack4_e4m3(a.x*4.0f, a.y*4.0f, a.z*4.0f, a.w*4.0f);
    }

    float f[16]; uint32_t u[16], d[16];
#pragma unroll
    for (int j = 0; j < 16; j++) {
        f[j] = x[rb + lane + 32*j];
        uint32_t b = __float_as_uint(f[j]);
        b = (b & 0x80000000u) ? ~b : (b | 0x80000000u);   // order-preserving
        u[j] = b >> 16;                                   // 16-bit key
        d[j] = u[j];
    }

    // ---- bitplane select of the KWTA-th largest 16-bit key ----
    uint32_t pfx = 0; int rem = KWTA;
#pragma unroll 1
    for (int bit = 15; bit >= 0; --bit) {
        int cl = 0;
#pragma unroll
        for (int j = 0; j < 16; j++) cl += ((d[j] >> bit) == 1u);
        int tot = __reduce_add_sync(FULL, cl);
        if (tot >= rem) {
            uint32_t bm = 1u << bit;
            pfx |= bm;
#pragma unroll
            for (int j = 0; j < 16; j++) d[j] ^= bm;
        } else {
            rem -= tot;
        }
    }

    int cgt = 0;
#pragma unroll
    for (int j = 0; j < 16; j++) cgt += (u[j] > pfx);
    const int need = KWTA - __reduce_add_sync(FULL, cgt);

    // ---- mask + phi/phi' (ties ranked by global index ascending) ----
    const float inv_sqrt2   = 0.7071067811865476f;
    const float inv_sqrt2pi = 0.3989422804014327f;
    int eq_before = 0;
#pragma unroll
    for (int j = 0; j < 16; j++) {
        bool eqj = (u[j] == pfx);
        unsigned bal = __ballot_sync(FULL, eqj);
        bool m = (u[j] > pfx) ||
                 (eqj && (eq_before + __popc(bal & ((1u << lane) - 1u))) < need);
        eq_before += __popc(bal);

        float v = f[j];
        float cdf = 0.5f * (1.0f + erff(v * inv_sqrt2));
        float pdf = expf(-0.5f * v * v) * inv_sqrt2pi;
        float ph = m ? v * cdf : 0.0f;
        float pd = m ? (cdf + v * pdf) : 0.0f;
        int i = lane + 32*j;
        sphi[wid][4 + i] = ph;
        g_phid_bf[rb + i] = __float2bfloat16(pd);
    }
    __syncwarp();

    // ---- phi -> fp8(x4), packed 4 consecutive per u32 ----
#pragma unroll
    for (int q = 0; q < 4; q++) {
        int w4 = lane + 32*q;
        float4 p = *(const float4*)&sphi[wid][4 + w4*4];
        ((uint32_t*)(g_phi_f8 + rb))[w4] =
            pack4_e4m3(p.x*4.0f, p.y*4.0f, p.z*4.0f, p.w*4.0f);
    }

    // ---- lateral stencil + base ----
#pragma unroll
    for (int j = 0; j < 16; j++) {
        int i = lane + 32*j;
        float lat = 0.0f;
#pragma unroll
        for (int d2 = 0; d2 < 7; d2++)
            lat = fmaf(sphi[wid][1 + i + d2], sSc[d2*DDIM + i], lat);
        float v = f[j];
        float sgn = (v > 0.0f) ? 1.0f : ((v < 0.0f) ? -1.0f : 0.0f);
        float bse = 0.3f*lat + 3.0f*td[rb + i] - 4.0f*v - 1e-6f*sgn;
        g_base_bf[rb + i] = __float2bfloat16(bse);
    }
}

// ------------------------------ FP8 GEMM ----------------------------------
// BM=128, BN=128, BK=128 (full 128B rows); 256 threads = 8 warps (4m x 2n),
// warp tile 32x64. 4 k-iters, 3-stage cp.async, 1 barrier/iter, 2 blocks/SM.
#define BM 128
#define BN 128
#define BK 128
#define NKIT (DDIM / BK)     // 4
#define ASTRIDE 144
#define B_OFF   (BM * ASTRIDE)             // 18432
#define BUFBYTES ((BM + BN) * ASTRIDE)     // 36864
#define GSTAGES 3
#define GSMEM (GSTAGES * BUFBYTES)         // 110592

__device__ __forceinline__ void gemm_mainloop(
    const uint8_t* __restrict__ A, const uint8_t* __restrict__ Bt,
    int m0, int n0, uint32_t sbase, int tid, int lane,
    int wm, int wn, float acc[2][8][4])
{
    // stage = A:128 rows x 8 chunks + B same = 2048 cpa16, 8/thread.
    auto load_stage = [&](int k0, int buf) {
        const uint32_t dA = sbase + buf*BUFBYTES;
        const uint32_t dB = dA + B_OFF;
#pragma unroll
        for (int i = 0; i < 4; i++) {
            int ch = i*256 + tid;            // 0..1023
            int r = ch >> 3, c = ch & 7;
            cpa16(dA + r*ASTRIDE + c*16,
                  A + (size_t)(m0 + r) * DDIM + k0*BK + c*16);
            cpa16(dB + r*ASTRIDE + c*16,
                  Bt + (size_t)(n0 + r) * DDIM + k0*BK + c*16);
        }
    };

    load_stage(0, 0); CP_COMMIT();
    load_stage(1, 1); CP_COMMIT();

    // fragment address components (fp8 m16n8k32 via ldmatrix.b16.x4)
    const int l7 = lane & 7;
    const int a_row  = wm*32 + ((lane>>3)&1)*8 + l7;   // + ma*16
    const int a_byte = ((lane>>4)&1)*16;
    const int b_row  = wn*64 + ((lane>>4)&1)*8 + l7;   // + p*16
    const int b_byte = ((lane>>3)&1)*16;

#pragma unroll 1
    for (int k0 = 0; k0 < NKIT; k0++) {
        const int buf = k0 % GSTAGES;
        CP_WAIT1();                 // <=1 pending -> stage k0 complete
        __syncthreads();

        if (k0 + 2 < NKIT) load_stage(k0 + 2, (k0 + 2) % GSTAGES);
        CP_COMMIT();                // always commit: uniform accounting

        const uint32_t abase = sbase + buf*BUFBYTES;
        const uint32_t bbase = abase + B_OFF;
#pragma unroll
        for (int ks = 0; ks < 4; ks++) {        // 4 x k32
            uint32_t a[2][4], bf[4][4];
#pragma unroll
            for (int ma = 0; ma < 2; ma++) {
                uint32_t ad = abase + (a_row + ma*16)*ASTRIDE + ks*32 + a_byte;
                LDMX4(a[ma][0], a[ma][1], a[ma][2], a[ma][3], ad);
            }
#pragma unroll
            for (int p = 0; p < 4; p++) {
                uint32_t bd = bbase + (b_row + p*16)*ASTRIDE + ks*32 + b_byte;
                LDMX4(bf[p][0], bf[p][1], bf[p][2], bf[p][3], bd);
            }
#pragma unroll
            for (int ma = 0; ma < 2; ma++)
#pragma unroll
                for (int nn = 0; nn < 8; nn++) {
                    int p = nn >> 1, off = (nn & 1)*2;
                    MMA_FP8(acc[ma][nn], a[ma][0], a[ma][1], a[ma][2], a[ma][3],
                            bf[p][off], bf[p][off + 1]);
                }
        }
    }
}

// merged gemm0/gemm1: blockIdx.z==0 -> rd, ==1 -> err
__global__ __launch_bounds__(256, 2)
void gemm01(const float* __restrict__ b_in, const float* __restrict__ b_out)
{
    extern __shared__ char smem[];
    const uint32_t sbase = smem_to_u32(smem);
    const int tid = threadIdx.x, wid = tid >> 5, lane = tid & 31;
    const int wm = wid & 3, wn = wid >> 2;
    const int m0 = blockIdx.y * BM, n0 = blockIdx.x * BN;
    const int mode = blockIdx.z;     // 0: rd, 1: err

    const uint8_t* A  = mode ? g_phi_f8 : g_bu_f8;
    const uint8_t* Bt = mode ? g_Wt_f8  : g_Vt_f8;
    const float* bias = mode ? b_out    : b_in;

    float acc[2][8][4];
#pragma unroll
    for (int i = 0; i < 2; i++)
#pragma unroll
        for (int j = 0; j < 8; j++)
#pragma unroll
            for (int q = 0; q < 4; q++) acc[i][j][q] = 0.0f;

    gemm_mainloop(A, Bt, m0, n0, sbase, tid, lane, wm, wn, acc);

    const int group = lane >> 2, qd = lane & 3;
#pragma unroll
    for (int ma = 0; ma < 2; ma++) {
#pragma unroll
        for (int nn = 0; nn < 8; nn++) {
            int col  = n0 + wn*64 + nn*8 + qd*2;
            int row0 = m0 + wm*32 + ma*16 + group;
#pragma unroll
            for (int h = 0; h < 2; h++) {
                int r = row0 + h*8;
                size_t idx = (size_t)r * DDIM + col;
                float v0 = acc[ma][nn][h*2]     * SCL_INV;
                float v1 = acc[ma][nn][h*2 + 1] * SCL_INV;
                float2 bs = *(const float2*)&bias[col];
                if (mode) {          // err = bu - (phi@W + b_out) -> fp8 x4
                    uint32_t bb = *(const uint32_t*)&g_bu_bf[idx];
                    float2 bu = __bfloat1622float2(*(__nv_bfloat162*)&bb);
                    float e0 = bu.x - (v0 + bs.x), e1 = bu.y - (v1 + bs.y);
                    *(uint16_t*)&g_err_f8[idx] = pack2_e4m3(e0*4.0f, e1*4.0f);
                } else {             // rd = bu@V + b_in + base -> bf16
                    uint32_t bb = *(const uint32_t*)&g_base_bf[idx];
                    float2 ba = __bfloat1622float2(*(__nv_bfloat162*)&bb);
                    __nv_bfloat162 o = __float22bfloat162_rn(
                        make_float2(v0 + bs.x + ba.x, v1 + bs.y + ba.y));
                    *(uint32_t*)&g_rd_bf[idx] = *(uint32_t*)&o;
                }
            }
        }
    }
}

__global__ __launch_bounds__(256, 2)
void gemm2()
{
    extern __shared__ char smem[];
    const uint32_t sbase = smem_to_u32(smem);
    const int tid = threadIdx.x, wid = tid >> 5, lane = tid & 31;
    const int wm = wid & 3, wn = wid >> 2;
    const int m0 = blockIdx.y * BM, n0 = blockIdx.x * BN;

    float acc[2][8][4];
#pragma unroll
    for (int i = 0; i < 2; i++)
#pragma unroll
        for (int j = 0; j < 8; j++)
#pragma unroll
            for (int q = 0; q < 4; q++) acc[i][j][q] = 0.0f;

    gemm_mainloop(g_err_f8, g_W_f8, m0, n0, sbase, tid, lane, wm, wn, acc);

    const int group = lane >> 2, qd = lane & 3;
    float lsum = 0.0f;
#pragma unroll
    for (int ma = 0; ma < 2; ma++) {
#pragma unroll
        for (int nn = 0; nn < 8; nn++) {
            int col  = n0 + wn*64 + nn*8 + qd*2;
            int row0 = m0 + wm*32 + ma*16 + group;
#pragma unroll
            for (int h = 0; h < 2; h++) {
                int r = row0 + h*8;
                size_t idx = (size_t)r * DDIM + col;
                float v0 = acc[ma][nn][h*2]     * SCL_INV;
                float v1 = acc[ma][nn][h*2 + 1] * SCL_INV;
                uint32_t pu = *(const uint32_t*)&g_phid_bf[idx];
                uint32_t ru = *(const uint32_t*)&g_rd_bf[idx];
                float2 ph = __bfloat1622float2(*(__nv_bfloat162*)&pu);
                float2 rd = __bfloat1622float2(*(__nv_bfloat162*)&ru);
                float s0 = fmaf(v0, ph.x, rd.x);
                float s1 = fmaf(v1, ph.y, rd.y);
                __nv_bfloat162 o = __float22bfloat162_rn(make_float2(s0, s1));
                *(uint32_t*)&g_sg_bf[idx] = *(uint32_t*)&o;
                lsum = fmaf(s0, s0, fmaf(s1, s1, lsum));
            }
        }
    }

    __shared__ float red[8];
#pragma unroll
    for (int o = 16; o > 0; o >>= 1) lsum += __shfl_xor_sync(0xffffffff, lsum, o);
    if (lane == 0) red[wid] = lsum;
    __syncthreads();
    if (tid == 0) {
        float s = 0.0f;
#pragma unroll
        for (int w = 0; w < 8; w++) s += red[w];
        atomicAdd(&g_norm2, (double)s);
    }
}

// ------------------------------ finalize ----------------------------------
__global__ __launch_bounds__(256) void finalize(const float* __restrict__ x,
                                                const int* __restrict__ step,
                                                float* __restrict__ out)
{
    float c = 0.5f * (0.8f / (1.0f + 0.1f * (float)(*step)));
    float n = c * (float)sqrt(g_norm2);
    float scale = (n > 1.0f) ? (c / (n + 1e-8f)) : c;

    size_t i8 = (size_t)(blockIdx.x * blockDim.x + threadIdx.x) * 8;
    uint4 su = *(const uint4*)&g_sg_bf[i8];
    const uint32_t* sp = (const uint32_t*)&su;
#pragma unroll
    for (int h = 0; h < 2; h++) {
        float4 xv = *(const float4*)(x + i8 + h*4);
        float2 sa = __bfloat1622float2(*(__nv_bfloat162*)&sp[h*2]);
        float2 sb = __bfloat1622float2(*(__nv_bfloat162*)&sp[h*2 + 1]);
        float4 o;
        o.x = fminf(5.0f, fmaxf(-5.0f, fmaf(scale, sa.x, xv.x)));
        o.y = fminf(5.0f, fmaxf(-5.0f, fmaf(scale, sa.y, xv.y)));
        o.z = fminf(5.0f, fmaxf(-5.0f, fmaf(scale, sb.x, xv.z)));
        o.w = fminf(5.0f, fmaxf(-5.0f, fmaf(scale, sb.y, xv.w)));
        *(float4*)(out + i8 + h*4) = o;
    }
}

// ---------------------------------------------------------------------------
extern "C" void kernel_launch(void* const* d_in, const int* in_sizes, int n_in,
                              void* d_out, int out_size)
{
    const float* bottom_up = (const float*)d_in[0];
    const float* td        = (const float*)d_in[1];
    const float* x         = (const float*)d_in[2];
    const float* V         = (const float*)d_in[3];
    const float* b_in      = (const float*)d_in[4];
    const float* W         = (const float*)d_in[5];
    const float* b_out     = (const float*)d_in[6];
    const float* L         = (const float*)d_in[7];
    const float* Lm        = (const float*)d_in[8];
    const int*   step      = (const int*)  d_in[9];
    float* out = (float*)d_out;

    cudaFuncSetAttribute(gemm01, cudaFuncAttributeMaxDynamicSharedMemorySize, GSMEM);
    cudaFuncSetAttribute(gemm2,  cudaFuncAttributeMaxDynamicSharedMemorySize, GSMEM);

    build_sc<<<2, 256>>>(L, Lm);
    prep_weights<<<dim3(16, 16), dim3(32, 8)>>>(W, V);
    rowprep<<<BDIM / 8, 256>>>(x, td, bottom_up);

    // z=0: rd = bu@V + b_in + base ; z=1: err = bu - (phi@W + b_out)
    gemm01<<<dim3(DDIM / BN, BDIM / BM, 2), 256, GSMEM>>>(b_in, b_out);
    // sg = (err@W^T)*phi' + rd ; ||sg||^2
    gemm2<<<dim3(DDIM / BN, BDIM / BM), 256, GSMEM>>>();

    finalize<<<NTOT / 8 / 256, 256>>>(x, step, out);
}

// round 16
// speedup vs baseline: 2.3518x; 1.0701x over previous
#include <cuda_runtime.h>
#include <cuda_bf16.h>
#include <math.h>
#include <stdint.h>

// ---------------------------------------------------------------------------
// PredictiveColumn on GB300 via mma.sync FP8 (e4m3).
//   build_sc     : transposed 7-tap band g_Sct[d][n] + zero norm
//   prep_weights : fp8 W / W^T / V^T (x16 scale) via tiled smem transpose
//   rowprep      : WARP-PER-ROW kWTA on top-16-bit keys, phi(fp8 x4),
//                  phi'(bf16), base(bf16), bu -> bf16 + fp8(x4)
//   gemm01 (z=0) : rd  = bu @ V + b_in + base -> bf16     (B = V^T fp8)
//   gemm01 (z=1) : err = bu - (phi @ W + b_out) -> fp8    (B = W^T fp8)
//   gemm2        : sg  = (err @ W^T)*phi' + rd -> bf16 ; ||sg||^2 (B = W fp8)
//   finalize     : out = clip(x + scale*sg, -5, 5)
// GEMM: 128x64 tile (warp 32x32, acc=32 regs), BK=128, 4 iters, 2-stage
// cp.async, 3 blocks/SM (24 warps/SM) -- concurrency, not bytes, binds.
// Scales: A x4, B x16, epilogue x(1/64).
// ---------------------------------------------------------------------------

#define BDIM 16384
#define DDIM 512
#define KWTA 128
#define NTOT (BDIM*DDIM)

__device__ uint8_t g_bu_f8 [NTOT];
__device__ uint8_t g_phi_f8[NTOT];
__device__ uint8_t g_err_f8[NTOT];
__device__ __nv_bfloat16 g_bu_bf  [NTOT];
__device__ __nv_bfloat16 g_phid_bf[NTOT];
__device__ __nv_bfloat16 g_base_bf[NTOT];
__device__ __nv_bfloat16 g_rd_bf  [NTOT];
__device__ __nv_bfloat16 g_sg_bf  [NTOT];
__device__ uint8_t g_W_f8 [DDIM*DDIM];
__device__ uint8_t g_Wt_f8[DDIM*DDIM];
__device__ uint8_t g_Vt_f8[DDIM*DDIM];
__device__ float  g_Sct[8*DDIM];     // [d][n], d=7 row is zero
__device__ double g_norm2;

#define SCL_INV 0.015625f            // 1/(4*16)

// ------------------------------ helpers -----------------------------------
__device__ __forceinline__ uint32_t smem_to_u32(const void* p) {
    uint32_t a;
    asm("{ .reg .u64 t; cvta.to.shared.u64 t, %1; cvt.u32.u64 %0, t; }" : "=r"(a) : "l"(p));
    return a;
}
__device__ __forceinline__ void cpa16(uint32_t dst, const void* src) {
    asm volatile("cp.async.cg.shared.global [%0], [%1], 16;" :: "r"(dst), "l"(src));
}
#define CP_COMMIT() asm volatile("cp.async.commit_group;" ::: "memory")
#define CP_WAIT1()  asm volatile("cp.async.wait_group 1;" ::: "memory")

#define LDMX4(r0, r1, r2, r3, addr) \
    asm volatile("ldmatrix.sync.aligned.m8n8.x4.shared.b16 {%0,%1,%2,%3}, [%4];" \
                 : "=r"(r0), "=r"(r1), "=r"(r2), "=r"(r3) : "r"(addr))

#define MMA_FP8(c, a0, a1, a2, a3, b0, b1) \
    asm volatile("mma.sync.aligned.m16n8k32.row.col.f32.e4m3.e4m3.f32 " \
                 "{%0,%1,%2,%3}, {%4,%5,%6,%7}, {%8,%9}, {%0,%1,%2,%3};" \
                 : "+f"((c)[0]), "+f"((c)[1]), "+f"((c)[2]), "+f"((c)[3]) \
                 : "r"(a0), "r"(a1), "r"(a2), "r"(a3), "r"(b0), "r"(b1))

// first source -> upper byte, second -> lower byte
__device__ __forceinline__ uint32_t pack4_e4m3(float f0, float f1, float f2, float f3) {
    uint16_t lo, hi;
    asm("cvt.rn.satfinite.e4m3x2.f32 %0, %1, %2;" : "=h"(lo) : "f"(f1), "f"(f0));
    asm("cvt.rn.satfinite.e4m3x2.f32 %0, %1, %2;" : "=h"(hi) : "f"(f3), "f"(f2));
    return (uint32_t)lo | ((uint32_t)hi << 16);
}
__device__ __forceinline__ uint16_t pack2_e4m3(float f0, float f1) {
    uint16_t r;
    asm("cvt.rn.satfinite.e4m3x2.f32 %0, %1, %2;" : "=h"(r) : "f"(f1), "f"(f0));
    return r;
}
__device__ __forceinline__ uint8_t cvt1_e4m3(float f) {
    uint16_t r;
    asm("cvt.rn.satfinite.e4m3x2.f32 %0, %1, %2;" : "=h"(r) : "f"(0.0f), "f"(f));
    return (uint8_t)r;
}

// ------------------------------ prep kernels ------------------------------
__global__ __launch_bounds__(256) void build_sc(const float* __restrict__ L,
                                                const float* __restrict__ Lm)
{
    int n = blockIdx.x * 256 + threadIdx.x;
    if (n == 0) g_norm2 = 0.0;
    if (n >= DDIM) return;
#pragma unroll
    for (int d = 0; d < 7; d++) {
        int j = n - 3 + d;
        float v = 0.0f;
        if (j >= 0 && j < DDIM) v = L[(size_t)j*DDIM + n] * Lm[(size_t)j*DDIM + n];
        g_Sct[d*DDIM + n] = v;
    }
    g_Sct[7*DDIM + n] = 0.0f;
}

// tiled transpose: W -> W_f8, Wt_f8 ; V -> Vt_f8 (all x16). 32x32 tiles.
__global__ __launch_bounds__(256) void prep_weights(const float* __restrict__ W,
                                                    const float* __restrict__ V)
{
    __shared__ float tw[32][33];
    __shared__ float tv[32][33];
    const int tx = threadIdx.x, ty = threadIdx.y;
    const int x0 = blockIdx.x * 32, y0 = blockIdx.y * 32;
#pragma unroll
    for (int r = 0; r < 4; r++) {
        int row = y0 + ty + r*8;
        float w = W[(size_t)row*DDIM + x0 + tx];
        float v = V[(size_t)row*DDIM + x0 + tx];
        tw[ty + r*8][tx] = w;
        tv[ty + r*8][tx] = v;
        g_W_f8[(size_t)row*DDIM + x0 + tx] = cvt1_e4m3(w * 16.0f);
    }
    __syncthreads();
#pragma unroll
    for (int r = 0; r < 4; r++) {
        int row = x0 + ty + r*8;
        g_Wt_f8[(size_t)row*DDIM + y0 + tx] = cvt1_e4m3(tw[tx][ty + r*8] * 16.0f);
        g_Vt_f8[(size_t)row*DDIM + y0 + tx] = cvt1_e4m3(tv[tx][ty + r*8] * 16.0f);
    }
}

// ------------------------------ rowprep -----------------------------------
__global__ __launch_bounds__(256) void rowprep(const float* __restrict__ x,
                                               const float* __restrict__ td,
                                               const float* __restrict__ bu)
{
    __shared__ float sSc[8*DDIM];       // taps, transposed [d][i]
    __shared__ float sphi[8][524];      // per-warp phi row, 4-guard front, 8 back

    const int tid = threadIdx.x, wid = tid >> 5, lane = tid & 31;
    const unsigned FULL = 0xffffffffu;

    for (int q = tid; q < 8*DDIM/4; q += 256)
        ((float4*)sSc)[q] = ((const float4*)g_Sct)[q];
    if (lane < 4) sphi[wid][lane] = 0.0f;
    if (lane < 8) sphi[wid][516 + lane] = 0.0f;
    __syncthreads();

    const size_t rb = ((size_t)blockIdx.x * 8 + wid) * DDIM;

    // ---- convert this row of bottom_up to bf16 + fp8(x4) ----
#pragma unroll
    for (int q = 0; q < 4; q++) {
        int f4 = lane + 32*q;                      // 128 float4 per row
        float4 a = ((const float4*)(bu + rb))[f4];
        __nv_bfloat162 lo = __float22bfloat162_rn(make_float2(a.x, a.y));
        __nv_bfloat162 hi = __float22bfloat162_rn(make_float2(a.z, a.w));
        uint2 o; o.x = *(uint32_t*)&lo; o.y = *(uint32_t*)&hi;
        ((uint2*)(g_bu_bf + rb))[f4] = o;
        ((uint32_t*)(g_bu_f8 + rb))[f4] =
            pack4_e4m3(a.x*4.0f, a.y*4.0f, a.z*4.0f, a.w*4.0f);
    }

    float f[16]; uint32_t u[16], d[16];
#pragma unroll
    for (int j = 0; j < 16; j++) {
        f[j] = x[rb + lane + 32*j];
        uint32_t b = __float_as_uint(f[j]);
        b = (b & 0x80000000u) ? ~b : (b | 0x80000000u);   // order-preserving
        u[j] = b >> 16;                                   // 16-bit key
        d[j] = u[j];
    }

    // ---- bitplane select of the KWTA-th largest 16-bit key ----
    uint32_t pfx = 0; int rem = KWTA;
#pragma unroll 1
    for (int bit = 15; bit >= 0; --bit) {
        int cl = 0;
#pragma unroll
        for (int j = 0; j < 16; j++) cl += ((d[j] >> bit) == 1u);
        int tot = __reduce_add_sync(FULL, cl);
        if (tot >= rem) {
            uint32_t bm = 1u << bit;
            pfx |= bm;
#pragma unroll
            for (int j = 0; j < 16; j++) d[j] ^= bm;
        } else {
            rem -= tot;
        }
    }

    int cgt = 0;
#pragma unroll
    for (int j = 0; j < 16; j++) cgt += (u[j] > pfx);
    const int need = KWTA - __reduce_add_sync(FULL, cgt);

    // ---- mask + phi/phi' (ties ranked by global index ascending) ----
    const float inv_sqrt2   = 0.7071067811865476f;
    const float inv_sqrt2pi = 0.3989422804014327f;
    int eq_before = 0;
#pragma unroll
    for (int j = 0; j < 16; j++) {
        bool eqj = (u[j] == pfx);
        unsigned bal = __ballot_sync(FULL, eqj);
        bool m = (u[j] > pfx) ||
                 (eqj && (eq_before + __popc(bal & ((1u << lane) - 1u))) < need);
        eq_before += __popc(bal);

        float v = f[j];
        float cdf = 0.5f * (1.0f + erff(v * inv_sqrt2));
        float pdf = expf(-0.5f * v * v) * inv_sqrt2pi;
        float ph = m ? v * cdf : 0.0f;
        float pd = m ? (cdf + v * pdf) : 0.0f;
        int i = lane + 32*j;
        sphi[wid][4 + i] = ph;
        g_phid_bf[rb + i] = __float2bfloat16(pd);
    }
    __syncwarp();

    // ---- phi -> fp8(x4), packed 4 consecutive per u32 ----
#pragma unroll
    for (int q = 0; q < 4; q++) {
        int w4 = lane + 32*q;
        float4 p = *(const float4*)&sphi[wid][4 + w4*4];
        ((uint32_t*)(g_phi_f8 + rb))[w4] =
            pack4_e4m3(p.x*4.0f, p.y*4.0f, p.z*4.0f, p.w*4.0f);
    }

    // ---- lateral stencil + base ----
#pragma unroll
    for (int j = 0; j < 16; j++) {
        int i = lane + 32*j;
        float lat = 0.0f;
#pragma unroll
        for (int d2 = 0; d2 < 7; d2++)
            lat = fmaf(sphi[wid][1 + i + d2], sSc[d2*DDIM + i], lat);
        float v = f[j];
        float sgn = (v > 0.0f) ? 1.0f : ((v < 0.0f) ? -1.0f : 0.0f);
        float bse = 0.3f*lat + 3.0f*td[rb + i] - 4.0f*v - 1e-6f*sgn;
        g_base_bf[rb + i] = __float2bfloat16(bse);
    }
}

// ------------------------------ FP8 GEMM ----------------------------------
// BM=128, BN=64, BK=128; 256 threads = 8 warps (4m x 2n), warp tile 32x32
// (acc = 32 regs/thread). 4 k-iters, 2-stage cp.async, 3 blocks/SM.
#define BM 128
#define BN 64
#define BK 128
#define NKIT (DDIM / BK)     // 4
#define ASTRIDE 144
#define B_OFF   (BM * ASTRIDE)             // 18432
#define BUFBYTES ((BM + BN) * ASTRIDE)     // 27648
#define GSMEM (2 * BUFBYTES)               // 55296

__device__ __forceinline__ void gemm_mainloop(
    const uint8_t* __restrict__ A, const uint8_t* __restrict__ Bt,
    int m0, int n0, uint32_t sbase, int tid, int lane,
    int wm, int wn, float acc[2][4][4])
{
    // stage = A:128 rows x 8 chunks (1024) + B:64 rows x 8 (512) = 6/thread
    auto load_stage = [&](int k0, int buf) {
        const uint32_t dS = sbase + buf*BUFBYTES;
#pragma unroll
        for (int i = 0; i < 4; i++) {
            int ch = i*256 + tid;            // A: 0..1023
            int r = ch >> 3, c = ch & 7;
            cpa16(dS + r*ASTRIDE + c*16,
                  A + (size_t)(m0 + r) * DDIM + k0*BK + c*16);
        }
#pragma unroll
        for (int i = 0; i < 2; i++) {        // B: 0..511
            int ch = i*256 + tid;
            int r = ch >> 3, c = ch & 7;
            cpa16(dS + B_OFF + r*ASTRIDE + c*16,
                  Bt + (size_t)(n0 + r) * DDIM + k0*BK + c*16);
        }
    };

    load_stage(0, 0);
    CP_COMMIT();

    // fragment address components (fp8 m16n8k32 via ldmatrix.b16.x4)
    const int l7 = lane & 7;
    const int a_row  = wm*32 + ((lane>>3)&1)*8 + l7;   // + ma*16
    const int a_byte = ((lane>>4)&1)*16;
    const int b_row  = wn*32 + ((lane>>4)&1)*8 + l7;   // + p*16
    const int b_byte = ((lane>>3)&1)*16;

#pragma unroll 1
    for (int k0 = 0; k0 < NKIT; k0++) {
        const int buf = k0 & 1;
        if (k0 + 1 < NKIT) load_stage(k0 + 1, buf ^ 1);
        CP_COMMIT();
        CP_WAIT1();                 // stage k0 complete (k0+1 may be pending)
        __syncthreads();

        const uint32_t abase = sbase + buf*BUFBYTES;
        const uint32_t bbase = abase + B_OFF;
#pragma unroll
        for (int ks = 0; ks < 4; ks++) {        // 4 x k32
            uint32_t a[2][4], bf[2][4];
#pragma unroll
            for (int ma = 0; ma < 2; ma++) {
                uint32_t ad = abase + (a_row + ma*16)*ASTRIDE + ks*32 + a_byte;
                LDMX4(a[ma][0], a[ma][1], a[ma][2], a[ma][3], ad);
            }
#pragma unroll
            for (int p = 0; p < 2; p++) {
                uint32_t bd = bbase + (b_row + p*16)*ASTRIDE + ks*32 + b_byte;
                LDMX4(bf[p][0], bf[p][1], bf[p][2], bf[p][3], bd);
            }
#pragma unroll
            for (int ma = 0; ma < 2; ma++)
#pragma unroll
                for (int nn = 0; nn < 4; nn++) {
                    int p = nn >> 1, off = (nn & 1)*2;
                    MMA_FP8(acc[ma][nn], a[ma][0], a[ma][1], a[ma][2], a[ma][3],
                            bf[p][off], bf[p][off + 1]);
                }
        }
        __syncthreads();            // all warps done reading buf before overwrite
    }
}

// merged gemm0/gemm1: blockIdx.z==0 -> rd, ==1 -> err
__global__ __launch_bounds__(256, 3)
void gemm01(const float* __restrict__ b_in, const float* __restrict__ b_out)
{
    extern __shared__ char smem[];
    const uint32_t sbase = smem_to_u32(smem);
    const int tid = threadIdx.x, wid = tid >> 5, lane = tid & 31;
    const int wm = wid & 3, wn = wid >> 2;
    const int m0 = blockIdx.y * BM, n0 = blockIdx.x * BN;
    const int mode = blockIdx.z;     // 0: rd, 1: err

    const uint8_t* A  = mode ? g_phi_f8 : g_bu_f8;
    const uint8_t* Bt = mode ? g_Wt_f8  : g_Vt_f8;
    const float* bias = mode ? b_out    : b_in;

    float acc[2][4][4];
#pragma unroll
    for (int i = 0; i < 2; i++)
#pragma unroll
        for (int j = 0; j < 4; j++)
#pragma unroll
            for (int q = 0; q < 4; q++) acc[i][j][q] = 0.0f;

    gemm_mainloop(A, Bt, m0, n0, sbase, tid, lane, wm, wn, acc);

    const int group = lane >> 2, qd = lane & 3;
#pragma unroll
    for (int ma = 0; ma < 2; ma++) {
#pragma unroll
        for (int nn = 0; nn < 4; nn++) {
            int col  = n0 + wn*32 + nn*8 + qd*2;
            int row0 = m0 + wm*32 + ma*16 + group;
#pragma unroll
            for (int h = 0; h < 2; h++) {
                int r = row0 + h*8;
                size_t idx = (size_t)r * DDIM + col;
                float v0 = acc[ma][nn][h*2]     * SCL_INV;
                float v1 = acc[ma][nn][h*2 + 1] * SCL_INV;
                float2 bs = *(const float2*)&bias[col];
                if (mode) {          // err = bu - (phi@W + b_out) -> fp8 x4
                    uint32_t bb = *(const uint32_t*)&g_bu_bf[idx];
                    float2 bu = __bfloat1622float2(*(__nv_bfloat162*)&bb);
                    float e0 = bu.x - (v0 + bs.x), e1 = bu.y - (v1 + bs.y);
                    *(uint16_t*)&g_err_f8[idx] = pack2_e4m3(e0*4.0f, e1*4.0f);
                } else {             // rd = bu@V + b_in + base -> bf16
                    uint32_t bb = *(const uint32_t*)&g_base_bf[idx];
                    float2 ba = __bfloat1622float2(*(__nv_bfloat162*)&bb);
                    __nv_bfloat162 o = __float22bfloat162_rn(
                        make_float2(v0 + bs.x + ba.x, v1 + bs.y + ba.y));
                    *(uint32_t*)&g_rd_bf[idx] = *(uint32_t*)&o;
                }
            }
        }
    }
}

__global__ __launch_bounds__(256, 3)
void gemm2()
{
    extern __shared__ char smem[];
    const uint32_t sbase = smem_to_u32(smem);
    const int tid = threadIdx.x, wid = tid >> 5, lane = tid & 31;
    const int wm = wid & 3, wn = wid >> 2;
    const int m0 = blockIdx.y * BM, n0 = blockIdx.x * BN;

    float acc[2][4][4];
#pragma unroll
    for (int i = 0; i < 2; i++)
#pragma unroll
        for (int j = 0; j < 4; j++)
#pragma unroll
            for (int q = 0; q < 4; q++) acc[i][j][q] = 0.0f;

    gemm_mainloop(g_err_f8, g_W_f8, m0, n0, sbase, tid, lane, wm, wn, acc);

    const int group = lane >> 2, qd = lane & 3;
    float lsum = 0.0f;
#pragma unroll
    for (int ma = 0; ma < 2; ma++) {
#pragma unroll
        for (int nn = 0; nn < 4; nn++) {
            int col  = n0 + wn*32 + nn*8 + qd*2;
            int row0 = m0 + wm*32 + ma*16 + group;
#pragma unroll
            for (int h = 0; h < 2; h++) {
                int r = row0 + h*8;
                size_t idx = (size_t)r * DDIM + col;
                float v0 = acc[ma][nn][h*2]     * SCL_INV;
                float v1 = acc[ma][nn][h*2 + 1] * SCL_INV;
                uint32_t pu = *(const uint32_t*)&g_phid_bf[idx];
                uint32_t ru = *(const uint32_t*)&g_rd_bf[idx];
                float2 ph = __bfloat1622float2(*(__nv_bfloat162*)&pu);
                float2 rd = __bfloat1622float2(*(__nv_bfloat162*)&ru);
                float s0 = fmaf(v0, ph.x, rd.x);
                float s1 = fmaf(v1, ph.y, rd.y);
                __nv_bfloat162 o = __float22bfloat162_rn(make_float2(s0, s1));
                *(uint32_t*)&g_sg_bf[idx] = *(uint32_t*)&o;
                lsum = fmaf(s0, s0, fmaf(s1, s1, lsum));
            }
        }
    }

    __shared__ float red[8];
#pragma unroll
    for (int o = 16; o > 0; o >>= 1) lsum += __shfl_xor_sync(0xffffffff, lsum, o);
    if (lane == 0) red[wid] = lsum;
    __syncthreads();
    if (tid == 0) {
        float s = 0.0f;
#pragma unroll
        for (int w = 0; w < 8; w++) s += red[w];
        atomicAdd(&g_norm2, (double)s);
    }
}

// ------------------------------ finalize ----------------------------------
__global__ __launch_bounds__(256) void finalize(const float* __restrict__ x,
                                                const int* __restrict__ step,
                                                float* __restrict__ out)
{
    float c = 0.5f * (0.8f / (1.0f + 0.1f * (float)(*step)));
    float n = c * (float)sqrt(g_norm2);
    float scale = (n > 1.0f) ? (c / (n + 1e-8f)) : c;

    size_t i8 = (size_t)(blockIdx.x * blockDim.x + threadIdx.x) * 8;
    uint4 su = *(const uint4*)&g_sg_bf[i8];
    const uint32_t* sp = (const uint32_t*)&su;
#pragma unroll
    for (int h = 0; h < 2; h++) {
        float4 xv = *(const float4*)(x + i8 + h*4);
        float2 sa = __bfloat1622float2(*(__nv_bfloat162*)&sp[h*2]);
        float2 sb = __bfloat1622float2(*(__nv_bfloat162*)&sp[h*2 + 1]);
        float4 o;
        o.x = fminf(5.0f, fmaxf(-5.0f, fmaf(scale, sa.x, xv.x)));
        o.y = fminf(5.0f, fmaxf(-5.0f, fmaf(scale, sa.y, xv.y)));
        o.z = fminf(5.0f, fmaxf(-5.0f, fmaf(scale, sb.x, xv.z)));
        o.w = fminf(5.0f, fmaxf(-5.0f, fmaf(scale, sb.y, xv.w)));
        *(float4*)(out + i8 + h*4) = o;
    }
}

// ---------------------------------------------------------------------------
extern "C" void kernel_launch(void* const* d_in, const int* in_sizes, int n_in,
                              void* d_out, int out_size)
{
    const float* bottom_up = (const float*)d_in[0];
    const float* td        = (const float*)d_in[1];
    const float* x         = (const float*)d_in[2];
    const float* V         = (const float*)d_in[3];
    const float* b_in      = (const float*)d_in[4];
    const float* W         = (const float*)d_in[5];
    const float* b_out     = (const float*)d_in[6];
    const float* L         = (const float*)d_in[7];
    const float* Lm        = (const float*)d_in[8];
    const int*   step      = (const int*)  d_in[9];
    float* out = (float*)d_out;

    cudaFuncSetAttribute(gemm01, cudaFuncAttributeMaxDynamicSharedMemorySize, GSMEM);
    cudaFuncSetAttribute(gemm2,  cudaFuncAttributeMaxDynamicSharedMemorySize, GSMEM);

    build_sc<<<2, 256>>>(L, Lm);
    prep_weights<<<dim3(16, 16), dim3(32, 8)>>>(W, V);
    rowprep<<<BDIM / 8, 256>>>(x, td, bottom_up);

    // z=0: rd = bu@V + b_in + base ; z=1: err = bu - (phi@W + b_out)
    gemm01<<<dim3(DDIM / BN, BDIM / BM, 2), 256, GSMEM>>>(b_in, b_out);
    // sg = (err@W^T)*phi' + rd ; ||sg||^2
    gemm2<<<dim3(DDIM / BN, BDIM / BM), 256, GSMEM>>>();

    finalize<<<NTOT / 8 / 256, 256>>>(x, step, out);
}